// round 3
// baseline (speedup 1.0000x reference)
#include <cuda_runtime.h>

#define NPTS 16384
#define CC 16
#define HH 256
#define WW 704
#define HWIMG (HH*WW)        // 180224
#define EPSBN 1e-3f
#define NB 128               // blocks for per-point kernels
#define NT 128               // threads  (NB*NT == NPTS, 1 point/thread)
#define SCANB 352            // HWIMG / 512
#define INVN (1.0f/16384.0f)

// ------------------------- device scratch (static, no allocs) ----------------
__device__ __align__(16) float g_val[HWIMG*CC];     // value table (HW,16)
__device__ __align__(16) float g_neigh[NPTS*CC];
__device__ __align__(16) float g_Y1[NPTS*CC];
__device__ __align__(16) float g_pts[NPTS*CC];
__device__ __align__(16) float g_Y3[NPTS*CC];
__device__ __align__(16) float g_Y4[NPTS*CC];
__device__ float g_pA[NB*34];
__device__ float g_p2[NB*37];
__device__ float g_p3[NB*32];
__device__ int g_cellCnt[HWIMG];
__device__ int g_cellStart[HWIMG+1];
__device__ int g_bs[SCANB];
__device__ int g_bo[SCANB];
__device__ int g_pidx[NPTS];

__device__ __forceinline__ float warpSum(float v){
#pragma unroll
  for(int o=16;o>0;o>>=1) v += __shfl_down_sync(0xffffffffu, v, o);
  return v;
}
__device__ __forceinline__ float warpMax(float v){
#pragma unroll
  for(int o=16;o>0;o>>=1) v = fmaxf(v, __shfl_down_sync(0xffffffffu, v, o));
  return v;
}

// ------------------------- counting sort of points into grid cells ----------
__global__ void k_zero(){
  int i = blockIdx.x*1024 + threadIdx.x;
  g_cellCnt[i] = 0;
}

__global__ void k_count(const int* __restrict__ grid){
  int n = blockIdx.x*NT + threadIdx.x;
  int cid = grid[2*n]*WW + grid[2*n+1];
  atomicAdd(&g_cellCnt[cid], 1);
}

__global__ void k_scan1(){
  __shared__ int sh[512];
  int t = threadIdx.x, b = blockIdx.x;
  int i = b*512 + t;
  int v = g_cellCnt[i];
  sh[t] = v; __syncthreads();
#pragma unroll
  for(int off=1; off<512; off<<=1){
    int x = (t>=off) ? sh[t-off] : 0;
    __syncthreads();
    sh[t] += x;
    __syncthreads();
  }
  g_cellStart[i] = sh[t] - v;          // exclusive within block
  if(t==511) g_bs[b] = sh[t];
}

__global__ void k_scan2(){
  __shared__ int sh[512];
  int t = threadIdx.x;
  int v = (t < SCANB) ? g_bs[t] : 0;
  sh[t] = v; __syncthreads();
#pragma unroll
  for(int off=1; off<512; off<<=1){
    int x = (t>=off) ? sh[t-off] : 0;
    __syncthreads();
    sh[t] += x;
    __syncthreads();
  }
  if(t < SCANB) g_bo[t] = sh[t] - v;   // exclusive block offsets
}

__global__ void k_scan3(){
  int t = threadIdx.x, b = blockIdx.x;
  g_cellStart[b*512 + t] += g_bo[b];
  if(b==0 && t==0) g_cellStart[HWIMG] = NPTS;
}

__global__ void k_scatter(const int* __restrict__ grid){
  int n = blockIdx.x*NT + threadIdx.x;
  int cid = grid[2*n]*WW + grid[2*n+1];
  int old = atomicSub(&g_cellCnt[cid], 1);
  g_pidx[g_cellStart[cid] + old - 1] = n;
}

// ------------------------- KNN (exact, lex tie-break) + neighbor mean -------
__device__ __forceinline__ void scan_cell(int cid, unsigned long long keyb,
    unsigned long long bk[9], unsigned long long &worst){
  int s = g_cellStart[cid];
  int e = g_cellStart[cid+1];
  for(; s<e; s++){
    unsigned long long key = keyb | (unsigned)g_pidx[s];
    if(key < worst){
      int pos = 8;
      while(pos>0 && key < bk[pos-1]){ bk[pos] = bk[pos-1]; pos--; }
      bk[pos] = key;
      worst = bk[8];
    }
  }
}

__global__ void __launch_bounds__(NT) k_knn(const int* __restrict__ grid,
                                            const float* __restrict__ imf){
  int n = blockIdx.x*NT + threadIdx.x;
  int qy = grid[2*n], qx = grid[2*n+1];
  unsigned long long bk[9];
#pragma unroll
  for(int i=0;i<9;i++) bk[i] = ~0ULL;
  unsigned long long worst = ~0ULL;

  for(int r=0; r<=960; r++){
    if(r==0){
      scan_cell(qy*WW+qx, 0ULL, bk, worst);
    } else {
      int xlo = qx-r; if(xlo<0) xlo=0;
      int xhi = qx+r; if(xhi>WW-1) xhi=WW-1;
      int dy2 = r*r;
      // top / bottom rows
#pragma unroll
      for(int sgn=0; sgn<2; sgn++){
        int y = sgn ? (qy+r) : (qy-r);
        if(y<0 || y>HH-1) continue;
        int base = y*WW;
        for(int x=xlo; x<=xhi; x++){
          int s = g_cellStart[base+x];
          int e = g_cellStart[base+x+1];
          if(s==e) continue;
          int dx = x-qx;
          unsigned long long keyb = ((unsigned long long)(dy2 + dx*dx)) << 14;
          for(; s<e; s++){
            unsigned long long key = keyb | (unsigned)g_pidx[s];
            if(key < worst){
              int pos=8;
              while(pos>0 && key<bk[pos-1]){ bk[pos]=bk[pos-1]; pos--; }
              bk[pos]=key; worst=bk[8];
            }
          }
        }
      }
      // left / right columns (exclude corners already done)
      int ylo = qy-r+1; if(ylo<0) ylo=0;
      int yhi = qy+r-1; if(yhi>HH-1) yhi=HH-1;
#pragma unroll
      for(int sgn=0; sgn<2; sgn++){
        int x = sgn ? (qx+r) : (qx-r);
        if(x<0 || x>WW-1) continue;
        for(int y=ylo; y<=yhi; y++){
          int cid = y*WW + x;
          int s = g_cellStart[cid];
          int e = g_cellStart[cid+1];
          if(s==e) continue;
          int dy = y-qy;
          unsigned long long keyb = ((unsigned long long)(dy*dy + dy2)) << 14;
          for(; s<e; s++){
            unsigned long long key = keyb | (unsigned)g_pidx[s];
            if(key < worst){
              int pos=8;
              while(pos>0 && key<bk[pos-1]){ bk[pos]=bk[pos-1]; pos--; }
              bk[pos]=key; worst=bk[8];
            }
          }
        }
      }
    }
    if(worst != ~0ULL){
      unsigned wd2 = (unsigned)(worst >> 14);
      unsigned nxt = (unsigned)((r+1)*(r+1));
      if(wd2 < nxt) break;
    }
  }

  // neighbors = entries 1..8 (entry 0 == lexicographically smallest, dropped)
  float acc[CC];
#pragma unroll
  for(int c=0;c<CC;c++) acc[c]=0.f;
#pragma unroll
  for(int i=1;i<9;i++){
    int j = (int)(bk[i] & 0x3FFFULL);
    int off = grid[2*j]*WW + grid[2*j+1];
#pragma unroll
    for(int c=0;c<CC;c++) acc[c] += imf[c*HWIMG + off];
  }
#pragma unroll
  for(int c=0;c<CC;c++) g_neigh[n*CC+c] = acc[c]*0.125f;
}

// ------------------------- value table: (HW,16) = imf^T @ Wval + bval -------
__global__ void __launch_bounds__(NT) k_val(const float* __restrict__ imf,
                                            const float* __restrict__ Wval,
                                            const float* __restrict__ bval){
  __shared__ float sW[CC*CC];
  __shared__ float sb[CC];
  int t = threadIdx.x;
  for(int i=t;i<CC*CC;i+=NT) sW[i]=Wval[i];
  if(t<CC) sb[t]=bval[t];
  __syncthreads();
  int p = blockIdx.x*NT + t;
  float x[CC];
#pragma unroll
  for(int c=0;c<CC;c++) x[c] = imf[c*HWIMG + p];
  float o[CC];
#pragma unroll
  for(int j=0;j<CC;j++){
    float s = sb[j];
#pragma unroll
    for(int c=0;c<CC;c++) s += x[c]*sW[c*CC+j];
    o[j]=s;
  }
  float4* dst = (float4*)(g_val + p*CC);
  dst[0] = make_float4(o[0],o[1],o[2],o[3]);
  dst[1] = make_float4(o[4],o[5],o[6],o[7]);
  dst[2] = make_float4(o[8],o[9],o[10],o[11]);
  dst[3] = make_float4(o[12],o[13],o[14],o[15]);
}

// ------------------------- stage A: Y1 = pf@Wk+bk, stats + grid sums --------
__global__ void __launch_bounds__(NT) k_A(const float* __restrict__ pf,
                                          const int* __restrict__ grid,
                                          const float* __restrict__ Wk,
                                          const float* __restrict__ bk){
  __shared__ float sW[CC*CC];
  __shared__ float sb[CC];
  __shared__ float red[4][34];
  int t = threadIdx.x;
  for(int i=t;i<CC*CC;i+=NT) sW[i]=Wk[i];
  if(t<CC) sb[t]=bk[t];
  __syncthreads();
  int n = blockIdx.x*NT + t;
  float x[CC];
#pragma unroll
  for(int c=0;c<CC;c++) x[c]=pf[n*CC+c];
  float y[CC];
#pragma unroll
  for(int j=0;j<CC;j++){
    float s=sb[j];
#pragma unroll
    for(int c=0;c<CC;c++) s += x[c]*sW[c*CC+j];
    y[j]=s;
    g_Y1[n*CC+j]=s;
  }
  float gy=(float)grid[2*n], gx=(float)grid[2*n+1];
  int lane=t&31, wid=t>>5;
#pragma unroll
  for(int c=0;c<CC;c++){ float s=warpSum(y[c]);      if(!lane) red[wid][c]=s; }
#pragma unroll
  for(int c=0;c<CC;c++){ float s=warpSum(y[c]*y[c]); if(!lane) red[wid][16+c]=s; }
  { float s=warpSum(gy); if(!lane) red[wid][32]=s; }
  { float s=warpSum(gx); if(!lane) red[wid][33]=s; }
  __syncthreads();
  if(t<34) g_pA[blockIdx.x*34+t] = red[0][t]+red[1][t]+red[2][t]+red[3][t];
}

// ------------------------- stage C: pts=BN1(Y1), Y3=pts@Wt+bt, rel moments --
__global__ void __launch_bounds__(NT) k_C(const int* __restrict__ grid,
                                          const float* __restrict__ gk,
                                          const float* __restrict__ betak,
                                          const float* __restrict__ Wt,
                                          const float* __restrict__ bt){
  __shared__ float sA[34];
  __shared__ float sa1[CC], sb1[CC], scc[2];
  __shared__ float sW[CC*CC], sbt[CC];
  __shared__ float red[4][37];
  int t = threadIdx.x;
  for(int i=t;i<CC*CC;i+=NT) sW[i]=Wt[i];
  if(t<CC) sbt[t]=bt[t];
  if(t<34){ float s=0.f; for(int e=0;e<NB;e++) s+=g_pA[e*34+t]; sA[t]=s; }
  __syncthreads();
  if(t<CC){
    float m = sA[t]*INVN;
    float v = sA[16+t]*INVN - m*m;
    float is = rsqrtf(v+EPSBN);
    sa1[t] = is*gk[t];
    sb1[t] = betak[t] - m*is*gk[t];
  }
  if(t==16) scc[0]=sA[32]*INVN;
  if(t==17) scc[1]=sA[33]*INVN;
  __syncthreads();
  int n = blockIdx.x*NT + t;
  float p[CC];
#pragma unroll
  for(int c=0;c<CC;c++){
    float v = g_Y1[n*CC+c]*sa1[c] + sb1[c];
    p[c]=v;
    g_pts[n*CC+c]=v;
  }
  float y3[CC];
#pragma unroll
  for(int j=0;j<CC;j++){
    float s=sbt[j];
#pragma unroll
    for(int c=0;c<CC;c++) s += p[c]*sW[c*CC+j];
    y3[j]=s;
    g_Y3[n*CC+j]=s;
  }
  float ry=(float)grid[2*n]-scc[0], rx=(float)grid[2*n+1]-scc[1];
  int lane=t&31, wid=t>>5;
#pragma unroll
  for(int c=0;c<CC;c++){ float s=warpSum(y3[c]);        if(!lane) red[wid][c]=s; }
#pragma unroll
  for(int c=0;c<CC;c++){ float s=warpSum(y3[c]*y3[c]);  if(!lane) red[wid][16+c]=s; }
  { float s=warpSum(ry*ry); if(!lane) red[wid][32]=s; }
  { float s=warpSum(rx*rx); if(!lane) red[wid][33]=s; }
  { float s=warpSum(ry*rx); if(!lane) red[wid][34]=s; }
  { float s=warpMax(fabsf(ry)); if(!lane) red[wid][35]=s; }
  { float s=warpMax(fabsf(rx)); if(!lane) red[wid][36]=s; }
  __syncthreads();
  if(t<35)      g_p2[blockIdx.x*37+t] = red[0][t]+red[1][t]+red[2][t]+red[3][t];
  else if(t<37) g_p2[blockIdx.x*37+t] = fmaxf(fmaxf(red[0][t],red[1][t]),fmaxf(red[2][t],red[3][t]));
}

// ------------------------- stage E: deform attn + fuse + Y4 stats -----------
__global__ void __launch_bounds__(NT) k_E(const int* __restrict__ grid,
    const float* __restrict__ Wfc, const float* __restrict__ gfc, const float* __restrict__ betafc,
    const float* __restrict__ gt,  const float* __restrict__ betat,
    const float* __restrict__ Woff,const float* __restrict__ boff,
    const float* __restrict__ Wattn,const float* __restrict__ battn,
    const float* __restrict__ Wout,const float* __restrict__ bout,
    const float* __restrict__ Wf,  const float* __restrict__ bf){
  __shared__ float sF[40];
  __shared__ float sWoff[CC*32], sWattn[CC*16], sWout[CC*16], sWf[32*CC];
  __shared__ float sboff[32], sbattn[16], sbout[16], sbf[16];
  __shared__ float sa3[16], sb3[16], su0[16], su1[16], sb2[16], sc[2];
  __shared__ float red[4][32];
  int t = threadIdx.x;
  for(int i=t;i<CC*32;i+=NT) sWoff[i]=Woff[i];
  for(int i=t;i<CC*16;i+=NT){ sWattn[i]=Wattn[i]; sWout[i]=Wout[i]; }
  for(int i=t;i<32*CC;i+=NT) sWf[i]=Wf[i];
  if(t<32) sboff[t]=boff[t];
  if(t<16){ sbattn[t]=battn[t]; sbout[t]=bout[t]; sbf[t]=bf[t]; }
  if(t<32){ float s=0.f; for(int e=0;e<NB;e++) s+=g_p2[e*37+t]; sF[t]=s; }
  else if(t<35){ float s=0.f; for(int e=0;e<NB;e++) s+=g_p2[e*37+t]; sF[t]=s; }
  else if(t<37){ float m=0.f; for(int e=0;e<NB;e++) m=fmaxf(m,g_p2[e*37+t]); sF[t]=m; }
  else if(t<39){ float s=0.f; for(int e=0;e<NB;e++) s+=g_pA[e*34+32+(t-37)]; sF[t]=s; }
  __syncthreads();
  if(t<16){
    float m3 = sF[t]*INVN;
    float v3 = sF[16+t]*INVN - m3*m3;
    float is3 = rsqrtf(v3+EPSBN);
    sa3[t] = is3*gt[t];
    sb3[t] = betat[t] - m3*is3*gt[t];
    float mxy = sF[35]; if(mxy==0.f) mxy=1.f;
    float mxx = sF[36]; if(mxx==0.f) mxx=1.f;
    float Syy=sF[32]*INVN, Sxx=sF[33]*INVN, Sxy=sF[34]*INVN;
    float w0 = Wfc[t]/mxy;
    float w1 = Wfc[16+t]/mxx;
    float v2 = w0*w0*Syy + 2.f*w0*w1*Sxy + w1*w1*Sxx;
    float a2 = rsqrtf(v2+EPSBN)*gfc[t];
    su0[t]=w0*a2; su1[t]=w1*a2; sb2[t]=betafc[t];
  }
  if(t==16){ sc[0]=sF[37]*INVN; sc[1]=sF[38]*INVN; }
  __syncthreads();

  int n = blockIdx.x*NT + t;
  float gy=(float)grid[2*n], gx=(float)grid[2*n+1];
  float ry=gy-sc[0], rx=gx-sc[1];
  float q[16];
#pragma unroll
  for(int c=0;c<16;c++)
    q[c] = g_pts[n*CC+c] + ry*su0[c] + rx*su1[c] + sb2[c];

  // attention (per-head softmax over 4 pts)
  float a[16];
#pragma unroll
  for(int hp=0;hp<16;hp++){
    float l=sbattn[hp];
#pragma unroll
    for(int c=0;c<16;c++) l += q[c]*sWattn[c*16+hp];
    a[hp]=l;
  }
#pragma unroll
  for(int h=0;h<4;h++){
    float m=fmaxf(fmaxf(a[4*h],a[4*h+1]),fmaxf(a[4*h+2],a[4*h+3]));
    float e0=expf(a[4*h]-m), e1=expf(a[4*h+1]-m), e2=expf(a[4*h+2]-m), e3=expf(a[4*h+3]-m);
    float inv=1.f/(e0+e1+e2+e3);
    a[4*h]=e0*inv; a[4*h+1]=e1*inv; a[4*h+2]=e2*inv; a[4*h+3]=e3*inv;
  }

  float acc[16];
#pragma unroll
  for(int c=0;c<16;c++) acc[c]=0.f;

#define CORNER(Yf,Xf,Wgt) do{ \
    float _y=(Yf), _x=(Xf); \
    if(_y>=0.f && _y<=(float)(HH-1) && _x>=0.f && _x<=(float)(WW-1)){ \
      int _i = ((int)_y)*WW + (int)_x; \
      const float4 _v = *(const float4*)(g_val + _i*CC + h*4); \
      float _w=(Wgt); \
      acc[h*4+0]+=_w*_v.x; acc[h*4+1]+=_w*_v.y; acc[h*4+2]+=_w*_v.z; acc[h*4+3]+=_w*_v.w; \
    } }while(0)

#pragma unroll
  for(int h=0;h<4;h++){
#pragma unroll
    for(int p=0;p<4;p++){
      float offy=sboff[h*8+p*2], offx=sboff[h*8+p*2+1];
#pragma unroll
      for(int c=0;c<16;c++){
        offy += q[c]*sWoff[c*32 + h*8+p*2];
        offx += q[c]*sWoff[c*32 + h*8+p*2+1];
      }
      float ly=gy+offy, lx=gx+offx;
      float fy=floorf(ly), fx=floorf(lx);
      float wy=ly-fy, wx=lx-fx;
      float ap=a[h*4+p];
      CORNER(fy,     fx,     ap*(1.f-wy)*(1.f-wx));
      CORNER(fy,     fx+1.f, ap*(1.f-wy)*wx);
      CORNER(fy+1.f, fx,     ap*wy*(1.f-wx));
      CORNER(fy+1.f, fx+1.f, ap*wy*wx);
    }
  }
#undef CORNER

  float img[16];
#pragma unroll
  for(int c=0;c<16;c++){
    float s=sbout[c];
#pragma unroll
    for(int k=0;k<16;k++) s += acc[k]*sWout[k*16+c];
    img[c] = s + g_neigh[n*CC+c];
  }
  float pp[16];
#pragma unroll
  for(int c=0;c<16;c++) pp[c] = g_Y3[n*CC+c]*sa3[c] + sb3[c];

  float y4[16];
#pragma unroll
  for(int c=0;c<16;c++){
    float s=sbf[c];
#pragma unroll
    for(int k=0;k<16;k++) s += fmaxf(pp[k],0.f)*sWf[k*16+c];
#pragma unroll
    for(int k=0;k<16;k++) s += fmaxf(img[k],0.f)*sWf[(16+k)*16+c];
    y4[c]=s;
    g_Y4[n*CC+c]=s;
  }
  int lane=t&31, wid=t>>5;
#pragma unroll
  for(int c=0;c<16;c++){ float s=warpSum(y4[c]);        if(!lane) red[wid][c]=s; }
#pragma unroll
  for(int c=0;c<16;c++){ float s=warpSum(y4[c]*y4[c]);  if(!lane) red[wid][16+c]=s; }
  __syncthreads();
  if(t<32) g_p3[blockIdx.x*32+t] = red[0][t]+red[1][t]+red[2][t]+red[3][t];
}

// ------------------------- stage G: final BN + relu -> d_out ----------------
__global__ void __launch_bounds__(NT) k_G(const float* __restrict__ gf,
                                          const float* __restrict__ betaf,
                                          float* __restrict__ out){
  __shared__ float sP[32];
  __shared__ float a4[16], b4[16];
  int t = threadIdx.x;
  if(t<32){ float s=0.f; for(int e=0;e<NB;e++) s+=g_p3[e*32+t]; sP[t]=s; }
  __syncthreads();
  if(t<16){
    float m = sP[t]*INVN;
    float v = sP[16+t]*INVN - m*m;
    float is = rsqrtf(v+EPSBN);
    a4[t]=is*gf[t];
    b4[t]=betaf[t] - m*is*gf[t];
  }
  __syncthreads();
  int n = blockIdx.x*NT + t;
#pragma unroll
  for(int c=0;c<16;c++)
    out[n*CC+c] = fmaxf(g_Y4[n*CC+c]*a4[c] + b4[c], 0.f);
}

// ------------------------- launch ------------------------------------------
extern "C" void kernel_launch(void* const* d_in, const int* in_sizes, int n_in,
                              void* d_out, int out_size){
  const float* pf     = (const float*)d_in[0];
  const float* imf    = (const float*)d_in[1];
  const int*   grid   = (const int*)  d_in[2];
  const float* Wk     = (const float*)d_in[3];
  const float* bk     = (const float*)d_in[4];
  const float* gk     = (const float*)d_in[5];
  const float* betak  = (const float*)d_in[6];
  const float* Wfc    = (const float*)d_in[7];
  /* bfc = d_in[8] cancels analytically (mean of pos_in == bfc) */
  const float* gfc    = (const float*)d_in[9];
  const float* betafc = (const float*)d_in[10];
  const float* Wt     = (const float*)d_in[11];
  const float* bt     = (const float*)d_in[12];
  const float* gt     = (const float*)d_in[13];
  const float* betat  = (const float*)d_in[14];
  const float* Woff   = (const float*)d_in[15];
  const float* boff   = (const float*)d_in[16];
  const float* Wattn  = (const float*)d_in[17];
  const float* battn  = (const float*)d_in[18];
  const float* Wval   = (const float*)d_in[19];
  const float* bval   = (const float*)d_in[20];
  const float* Wout   = (const float*)d_in[21];
  const float* bout   = (const float*)d_in[22];
  const float* Wf     = (const float*)d_in[23];
  const float* bf     = (const float*)d_in[24];
  const float* gf     = (const float*)d_in[25];
  const float* betaf  = (const float*)d_in[26];
  float* out = (float*)d_out;

  k_zero   <<<HWIMG/1024, 1024>>>();
  k_count  <<<NB, NT>>>(grid);
  k_scan1  <<<SCANB, 512>>>();
  k_scan2  <<<1, 512>>>();
  k_scan3  <<<SCANB, 512>>>();
  k_scatter<<<NB, NT>>>(grid);
  k_val    <<<HWIMG/NT, NT>>>(imf, Wval, bval);
  k_knn    <<<NB, NT>>>(grid, imf);
  k_A      <<<NB, NT>>>(pf, grid, Wk, bk);
  k_C      <<<NB, NT>>>(grid, gk, betak, Wt, bt);
  k_E      <<<NB, NT>>>(grid, Wfc, gfc, betafc, gt, betat,
                        Woff, boff, Wattn, battn, Wout, bout, Wf, bf);
  k_G      <<<NB, NT>>>(gf, betaf, out);
}

// round 4
// speedup vs baseline: 1.1969x; 1.1969x over previous
#include <cuda_runtime.h>

#define NPTS 16384
#define CC 16
#define HH 256
#define WW 704
#define HWIMG (HH*WW)        // 180224
#define EPSBN 1e-3f
#define NB 128               // blocks for per-point kernels
#define NT 128               // threads  (NB*NT == NPTS)
#define SCANB 352            // HWIMG / 512
#define INVN (1.0f/16384.0f)

// ------------------------- device scratch (static, no allocs) ----------------
__device__ __align__(16) float g_val[HWIMG*CC];     // value table (HW,16)
__device__ __align__(16) float g_imt[HWIMG*CC];     // transposed image feat (HW,16)
__device__ __align__(16) float g_Y1[NPTS*CC];
__device__ __align__(16) float g_pts[NPTS*CC];
__device__ __align__(16) float g_Y3[NPTS*CC];
__device__ __align__(16) float g_Y4[NPTS*CC];
__device__ float g_pA[NB*34];
__device__ float g_p2[NB*37];
__device__ float g_p3[NB*32];
__device__ int g_cellCnt[HWIMG];
__device__ int g_cellStart[HWIMG+1];
__device__ int g_bs[SCANB];
__device__ unsigned g_packed[NPTS];   // (y<<24)|(x<<14)|idx, sorted by cell

__device__ __forceinline__ float warpSum(float v){
#pragma unroll
  for(int o=16;o>0;o>>=1) v += __shfl_down_sync(0xffffffffu, v, o);
  return v;
}
__device__ __forceinline__ float warpMax(float v){
#pragma unroll
  for(int o=16;o>0;o>>=1) v = fmaxf(v, __shfl_down_sync(0xffffffffu, v, o));
  return v;
}

// ------------------------- K1: zero counts + value table + imf transpose ----
__global__ void __launch_bounds__(NT) k_init(const float* __restrict__ imf,
                                             const float* __restrict__ Wval,
                                             const float* __restrict__ bval){
  __shared__ float sW[CC*CC];
  __shared__ float sb[CC];
  int t = threadIdx.x;
  for(int i=t;i<CC*CC;i+=NT) sW[i]=Wval[i];
  if(t<CC) sb[t]=bval[t];
  __syncthreads();
  int p = blockIdx.x*NT + t;
  g_cellCnt[p] = 0;
  float x[CC];
#pragma unroll
  for(int c=0;c<CC;c++) x[c] = imf[c*HWIMG + p];
  float4* it = (float4*)(g_imt + p*CC);
  it[0] = make_float4(x[0],x[1],x[2],x[3]);
  it[1] = make_float4(x[4],x[5],x[6],x[7]);
  it[2] = make_float4(x[8],x[9],x[10],x[11]);
  it[3] = make_float4(x[12],x[13],x[14],x[15]);
  float o[CC];
#pragma unroll
  for(int j=0;j<CC;j++){
    float s = sb[j];
#pragma unroll
    for(int c=0;c<CC;c++) s += x[c]*sW[c*CC+j];
    o[j]=s;
  }
  float4* dst = (float4*)(g_val + p*CC);
  dst[0] = make_float4(o[0],o[1],o[2],o[3]);
  dst[1] = make_float4(o[4],o[5],o[6],o[7]);
  dst[2] = make_float4(o[8],o[9],o[10],o[11]);
  dst[3] = make_float4(o[12],o[13],o[14],o[15]);
}

// ------------------------- K2: cell count + Y1 = pf@Wk+bk + stats -----------
__global__ void __launch_bounds__(NT) k_A(const float* __restrict__ pf,
                                          const int* __restrict__ grid,
                                          const float* __restrict__ Wk,
                                          const float* __restrict__ bk){
  __shared__ float sW[CC*CC];
  __shared__ float sb[CC];
  __shared__ float red[4][34];
  int t = threadIdx.x;
  for(int i=t;i<CC*CC;i+=NT) sW[i]=Wk[i];
  if(t<CC) sb[t]=bk[t];
  __syncthreads();
  int n = blockIdx.x*NT + t;
  int gyi = grid[2*n], gxi = grid[2*n+1];
  atomicAdd(&g_cellCnt[gyi*WW + gxi], 1);
  float x[CC];
#pragma unroll
  for(int c=0;c<CC;c++) x[c]=pf[n*CC+c];
  float y[CC];
#pragma unroll
  for(int j=0;j<CC;j++){
    float s=sb[j];
#pragma unroll
    for(int c=0;c<CC;c++) s += x[c]*sW[c*CC+j];
    y[j]=s;
    g_Y1[n*CC+j]=s;
  }
  float gy=(float)gyi, gx=(float)gxi;
  int lane=t&31, wid=t>>5;
#pragma unroll
  for(int c=0;c<CC;c++){ float s=warpSum(y[c]);      if(!lane) red[wid][c]=s; }
#pragma unroll
  for(int c=0;c<CC;c++){ float s=warpSum(y[c]*y[c]); if(!lane) red[wid][16+c]=s; }
  { float s=warpSum(gy); if(!lane) red[wid][32]=s; }
  { float s=warpSum(gx); if(!lane) red[wid][33]=s; }
  __syncthreads();
  if(t<34) g_pA[blockIdx.x*34+t] = red[0][t]+red[1][t]+red[2][t]+red[3][t];
}

// ------------------------- K3: per-block scan of cell counts ----------------
__global__ void k_scan1(){
  __shared__ int sh[512];
  int t = threadIdx.x, b = blockIdx.x;
  int i = b*512 + t;
  int v = g_cellCnt[i];
  sh[t] = v; __syncthreads();
#pragma unroll
  for(int off=1; off<512; off<<=1){
    int x = (t>=off) ? sh[t-off] : 0;
    __syncthreads();
    sh[t] += x;
    __syncthreads();
  }
  g_cellStart[i] = sh[t] - v;          // exclusive within block
  if(t==511) g_bs[b] = sh[t];
}

// ------------------------- K4: fused block-offset + add ---------------------
__global__ void k_scan23(){
  __shared__ int ssum[16];
  __shared__ int soff;
  int t = threadIdx.x, b = blockIdx.x;
  int v = (t < b && t < SCANB) ? g_bs[t] : 0;
#pragma unroll
  for(int o=16;o>0;o>>=1) v += __shfl_down_sync(0xffffffffu, v, o);
  if((t&31)==0) ssum[t>>5]=v;
  __syncthreads();
  if(t==0){ int s=0;
#pragma unroll
    for(int i=0;i<16;i++) s+=ssum[i];
    soff=s; }
  __syncthreads();
  g_cellStart[b*512 + t] += soff;
  if(b==0 && t==0) g_cellStart[HWIMG] = NPTS;
}

// ------------------------- K5: scatter packed points + stage C --------------
__global__ void __launch_bounds__(NT) k_C(const int* __restrict__ grid,
                                          const float* __restrict__ gk,
                                          const float* __restrict__ betak,
                                          const float* __restrict__ Wt,
                                          const float* __restrict__ bt){
  __shared__ float sA[34];
  __shared__ float sa1[CC], sb1[CC], scc[2];
  __shared__ float sW[CC*CC], sbt[CC];
  __shared__ float red[4][37];
  int t = threadIdx.x;
  for(int i=t;i<CC*CC;i+=NT) sW[i]=Wt[i];
  if(t<CC) sbt[t]=bt[t];
  if(t<34){ float s=0.f; for(int e=0;e<NB;e++) s+=g_pA[e*34+t]; sA[t]=s; }
  __syncthreads();
  if(t<CC){
    float m = sA[t]*INVN;
    float v = sA[16+t]*INVN - m*m;
    float is = rsqrtf(v+EPSBN);
    sa1[t] = is*gk[t];
    sb1[t] = betak[t] - m*is*gk[t];
  }
  if(t==16) scc[0]=sA[32]*INVN;
  if(t==17) scc[1]=sA[33]*INVN;
  __syncthreads();
  int n = blockIdx.x*NT + t;
  int gyi = grid[2*n], gxi = grid[2*n+1];
  // scatter into sorted packed list (order within cell irrelevant: keys carry idx)
  {
    int cid = gyi*WW + gxi;
    int old = atomicSub(&g_cellCnt[cid], 1);
    g_packed[g_cellStart[cid] + old - 1] =
        ((unsigned)gyi<<24) | ((unsigned)gxi<<14) | (unsigned)n;
  }
  float p[CC];
#pragma unroll
  for(int c=0;c<CC;c++){
    float v = g_Y1[n*CC+c]*sa1[c] + sb1[c];
    p[c]=v;
    g_pts[n*CC+c]=v;
  }
  float y3[CC];
#pragma unroll
  for(int j=0;j<CC;j++){
    float s=sbt[j];
#pragma unroll
    for(int c=0;c<CC;c++) s += p[c]*sW[c*CC+j];
    y3[j]=s;
    g_Y3[n*CC+j]=s;
  }
  float ry=(float)gyi-scc[0], rx=(float)gxi-scc[1];
  int lane=t&31, wid=t>>5;
#pragma unroll
  for(int c=0;c<CC;c++){ float s=warpSum(y3[c]);        if(!lane) red[wid][c]=s; }
#pragma unroll
  for(int c=0;c<CC;c++){ float s=warpSum(y3[c]*y3[c]);  if(!lane) red[wid][16+c]=s; }
  { float s=warpSum(ry*ry); if(!lane) red[wid][32]=s; }
  { float s=warpSum(rx*rx); if(!lane) red[wid][33]=s; }
  { float s=warpSum(ry*rx); if(!lane) red[wid][34]=s; }
  { float s=warpMax(fabsf(ry)); if(!lane) red[wid][35]=s; }
  { float s=warpMax(fabsf(rx)); if(!lane) red[wid][36]=s; }
  __syncthreads();
  if(t<35)      g_p2[blockIdx.x*37+t] = red[0][t]+red[1][t]+red[2][t]+red[3][t];
  else if(t<37) g_p2[blockIdx.x*37+t] = fmaxf(fmaxf(red[0][t],red[1][t]),fmaxf(red[2][t],red[3][t]));
}

// ------------------------- KNN helpers --------------------------------------
__device__ __forceinline__ void insert9(unsigned long long key,
    unsigned long long bk[9], unsigned long long &worst){
  if(key < worst){
    int pos = 8;
    while(pos>0 && key < bk[pos-1]){ bk[pos] = bk[pos-1]; pos--; }
    bk[pos] = key;
    worst = bk[8];
  }
}

__device__ __forceinline__ void scan_range(int s, int e, int qy, int qx,
    unsigned long long bk[9], unsigned long long &worst){
  for(; s<e; s++){
    unsigned p = g_packed[s];
    int dy = (int)(p>>24) - qy;
    int dx = (int)((p>>14)&0x3FFu) - qx;
    unsigned d2 = (unsigned)(dy*dy + dx*dx);
    unsigned long long key = ((unsigned long long)d2<<14) | (p & 0x3FFFu);
    if(key < worst){
      int pos = 8;
      while(pos>0 && key < bk[pos-1]){ bk[pos] = bk[pos-1]; pos--; }
      bk[pos] = key;
      worst = bk[8];
    }
  }
}

__device__ __forceinline__ int isqrt_dev(int v){
  if(v < 0) return -1;
  int h = (int)sqrtf((float)v);
  while((h+1)*(h+1) <= v) h++;
  while(h>0 && h*h > v) h--;
  return h;
}

// ------------------------- K6: KNN + neighbor mean + deform attn + fuse -----
__global__ void __launch_bounds__(NT) k_E(const int* __restrict__ grid,
    const float* __restrict__ Wfc, const float* __restrict__ gfc, const float* __restrict__ betafc,
    const float* __restrict__ gt,  const float* __restrict__ betat,
    const float* __restrict__ Woff,const float* __restrict__ boff,
    const float* __restrict__ Wattn,const float* __restrict__ battn,
    const float* __restrict__ Wout,const float* __restrict__ bout,
    const float* __restrict__ Wf,  const float* __restrict__ bf){
  __shared__ float sF[40];
  __shared__ float sWoff[CC*32], sWattn[CC*16], sWout[CC*16], sWf[32*CC];
  __shared__ float sboff[32], sbattn[16], sbout[16], sbf[16];
  __shared__ float sa3[16], sb3[16], su0[16], su1[16], sb2[16], sc[2];
  __shared__ float red[4][32];
  int t = threadIdx.x;
  for(int i=t;i<CC*32;i+=NT) sWoff[i]=Woff[i];
  for(int i=t;i<CC*16;i+=NT){ sWattn[i]=Wattn[i]; sWout[i]=Wout[i]; }
  for(int i=t;i<32*CC;i+=NT) sWf[i]=Wf[i];
  if(t<32) sboff[t]=boff[t];
  if(t<16){ sbattn[t]=battn[t]; sbout[t]=bout[t]; sbf[t]=bf[t]; }
  if(t<35){ float s=0.f; for(int e=0;e<NB;e++) s+=g_p2[e*37+t]; sF[t]=s; }
  else if(t<37){ float m=0.f; for(int e=0;e<NB;e++) m=fmaxf(m,g_p2[e*37+t]); sF[t]=m; }
  else if(t<39){ float s=0.f; for(int e=0;e<NB;e++) s+=g_pA[e*34+32+(t-37)]; sF[t]=s; }
  __syncthreads();
  if(t<16){
    float m3 = sF[t]*INVN;
    float v3 = sF[16+t]*INVN - m3*m3;
    float is3 = rsqrtf(v3+EPSBN);
    sa3[t] = is3*gt[t];
    sb3[t] = betat[t] - m3*is3*gt[t];
    float mxy = sF[35]; if(mxy==0.f) mxy=1.f;
    float mxx = sF[36]; if(mxx==0.f) mxx=1.f;
    float Syy=sF[32]*INVN, Sxx=sF[33]*INVN, Sxy=sF[34]*INVN;
    float w0 = Wfc[t]/mxy;
    float w1 = Wfc[16+t]/mxx;
    float v2 = w0*w0*Syy + 2.f*w0*w1*Sxy + w1*w1*Sxx;
    float a2 = rsqrtf(v2+EPSBN)*gfc[t];
    su0[t]=w0*a2; su1[t]=w1*a2; sb2[t]=betafc[t];
  }
  if(t==16){ sc[0]=sF[37]*INVN; sc[1]=sF[38]*INVN; }
  __syncthreads();

  int n = blockIdx.x*NT + t;
  int qyi = grid[2*n], qxi = grid[2*n+1];

  // ---------------- exact KNN: windowed row-range pass + exact fallback -----
  unsigned long long bk[9];
#pragma unroll
  for(int i=0;i<9;i++) bk[i] = ~0ULL;
  unsigned long long worst = ~0ULL;
  {
    int xlo = qxi-12; if(xlo<0) xlo=0;
    int xhi = qxi+12; if(xhi>WW-1) xhi=WW-1;
    int ylo = qyi-12; if(ylo<0) ylo=0;
    int yhi = qyi+12; if(yhi>HH-1) yhi=HH-1;
    for(int y=ylo; y<=yhi; y++){
      int base = y*WW;
      scan_range(g_cellStart[base+xlo], g_cellStart[base+xhi+1], qyi, qxi, bk, worst);
    }
  }
  if(worst == ~0ULL || (worst>>14) > 168ULL){
    // rare exact fallback: restart with adaptive row expansion
#pragma unroll
    for(int i=0;i<9;i++) bk[i] = ~0ULL;
    worst = ~0ULL;
    for(int d=0; d<1024; d++){
      if(worst != ~0ULL && (unsigned long long)(d*d) > (worst>>14)) break;
#pragma unroll
      for(int sgn=0; sgn<2; sgn++){
        if(d==0 && sgn) break;
        int y = sgn ? qyi+d : qyi-d;
        if((unsigned)y >= HH) continue;
        int xlo=0, xhi=WW-1;
        if(worst != ~0ULL){
          int v = (int)(worst>>14) - d*d;
          int hw = isqrt_dev(v);
          if(hw < 0) continue;
          xlo = qxi-hw; if(xlo<0) xlo=0;
          xhi = qxi+hw; if(xhi>WW-1) xhi=WW-1;
        }
        scan_range(g_cellStart[y*WW+xlo], g_cellStart[y*WW+xhi+1], qyi, qxi, bk, worst);
      }
    }
  }

  // neighbor mean over entries 1..8 (entry 0 = lexicographic min, dropped)
  float nb0[16];
#pragma unroll
  for(int c=0;c<16;c++) nb0[c]=0.f;
#pragma unroll
  for(int i=1;i<9;i++){
    int j = (int)(bk[i] & 0x3FFFULL);
    int off = grid[2*j]*WW + grid[2*j+1];
    const float4* vv = (const float4*)(g_imt + off*CC);
    float4 a0=vv[0], a1=vv[1], a2=vv[2], a3=vv[3];
    nb0[0]+=a0.x; nb0[1]+=a0.y; nb0[2]+=a0.z; nb0[3]+=a0.w;
    nb0[4]+=a1.x; nb0[5]+=a1.y; nb0[6]+=a1.z; nb0[7]+=a1.w;
    nb0[8]+=a2.x; nb0[9]+=a2.y; nb0[10]+=a2.z; nb0[11]+=a2.w;
    nb0[12]+=a3.x; nb0[13]+=a3.y; nb0[14]+=a3.z; nb0[15]+=a3.w;
  }

  // ---------------- stage E proper ------------------------------------------
  float gy=(float)qyi, gx=(float)qxi;
  float ry=gy-sc[0], rx=gx-sc[1];
  float q[16];
#pragma unroll
  for(int c=0;c<16;c++)
    q[c] = g_pts[n*CC+c] + ry*su0[c] + rx*su1[c] + sb2[c];

  float a[16];
#pragma unroll
  for(int hp=0;hp<16;hp++){
    float l=sbattn[hp];
#pragma unroll
    for(int c=0;c<16;c++) l += q[c]*sWattn[c*16+hp];
    a[hp]=l;
  }
#pragma unroll
  for(int h=0;h<4;h++){
    float m=fmaxf(fmaxf(a[4*h],a[4*h+1]),fmaxf(a[4*h+2],a[4*h+3]));
    float e0=expf(a[4*h]-m), e1=expf(a[4*h+1]-m), e2=expf(a[4*h+2]-m), e3=expf(a[4*h+3]-m);
    float inv=1.f/(e0+e1+e2+e3);
    a[4*h]=e0*inv; a[4*h+1]=e1*inv; a[4*h+2]=e2*inv; a[4*h+3]=e3*inv;
  }

  float acc[16];
#pragma unroll
  for(int c=0;c<16;c++) acc[c]=0.f;

#define CORNER(Yf,Xf,Wgt) do{ \
    float _y=(Yf), _x=(Xf); \
    if(_y>=0.f && _y<=(float)(HH-1) && _x>=0.f && _x<=(float)(WW-1)){ \
      int _i = ((int)_y)*WW + (int)_x; \
      const float4 _v = *(const float4*)(g_val + _i*CC + h*4); \
      float _w=(Wgt); \
      acc[h*4+0]+=_w*_v.x; acc[h*4+1]+=_w*_v.y; acc[h*4+2]+=_w*_v.z; acc[h*4+3]+=_w*_v.w; \
    } }while(0)

#pragma unroll
  for(int h=0;h<4;h++){
#pragma unroll
    for(int p=0;p<4;p++){
      float offy=sboff[h*8+p*2], offx=sboff[h*8+p*2+1];
#pragma unroll
      for(int c=0;c<16;c++){
        offy += q[c]*sWoff[c*32 + h*8+p*2];
        offx += q[c]*sWoff[c*32 + h*8+p*2+1];
      }
      float ly=gy+offy, lx=gx+offx;
      float fy=floorf(ly), fx=floorf(lx);
      float wy=ly-fy, wx=lx-fx;
      float ap=a[h*4+p];
      CORNER(fy,     fx,     ap*(1.f-wy)*(1.f-wx));
      CORNER(fy,     fx+1.f, ap*(1.f-wy)*wx);
      CORNER(fy+1.f, fx,     ap*wy*(1.f-wx));
      CORNER(fy+1.f, fx+1.f, ap*wy*wx);
    }
  }
#undef CORNER

  float img[16];
#pragma unroll
  for(int c=0;c<16;c++){
    float s=sbout[c];
#pragma unroll
    for(int k=0;k<16;k++) s += acc[k]*sWout[k*16+c];
    img[c] = s + nb0[c]*0.125f;
  }
  float pp[16];
#pragma unroll
  for(int c=0;c<16;c++) pp[c] = g_Y3[n*CC+c]*sa3[c] + sb3[c];

  float y4[16];
#pragma unroll
  for(int c=0;c<16;c++){
    float s=sbf[c];
#pragma unroll
    for(int k=0;k<16;k++) s += fmaxf(pp[k],0.f)*sWf[k*16+c];
#pragma unroll
    for(int k=0;k<16;k++) s += fmaxf(img[k],0.f)*sWf[(16+k)*16+c];
    y4[c]=s;
    g_Y4[n*CC+c]=s;
  }
  int lane=t&31, wid=t>>5;
#pragma unroll
  for(int c=0;c<16;c++){ float s=warpSum(y4[c]);        if(!lane) red[wid][c]=s; }
#pragma unroll
  for(int c=0;c<16;c++){ float s=warpSum(y4[c]*y4[c]);  if(!lane) red[wid][16+c]=s; }
  __syncthreads();
  if(t<32) g_p3[blockIdx.x*32+t] = red[0][t]+red[1][t]+red[2][t]+red[3][t];
}

// ------------------------- K7: final BN + relu -> d_out ---------------------
__global__ void __launch_bounds__(NT) k_G(const float* __restrict__ gf,
                                          const float* __restrict__ betaf,
                                          float* __restrict__ out){
  __shared__ float sP[32];
  __shared__ float a4[16], b4[16];
  int t = threadIdx.x;
  if(t<32){ float s=0.f; for(int e=0;e<NB;e++) s+=g_p3[e*32+t]; sP[t]=s; }
  __syncthreads();
  if(t<16){
    float m = sP[t]*INVN;
    float v = sP[16+t]*INVN - m*m;
    float is = rsqrtf(v+EPSBN);
    a4[t]=is*gf[t];
    b4[t]=betaf[t] - m*is*gf[t];
  }
  __syncthreads();
  int n = blockIdx.x*NT + t;
#pragma unroll
  for(int c=0;c<16;c++)
    out[n*CC+c] = fmaxf(g_Y4[n*CC+c]*a4[c] + b4[c], 0.f);
}

// ------------------------- launch ------------------------------------------
extern "C" void kernel_launch(void* const* d_in, const int* in_sizes, int n_in,
                              void* d_out, int out_size){
  const float* pf     = (const float*)d_in[0];
  const float* imf    = (const float*)d_in[1];
  const int*   grid   = (const int*)  d_in[2];
  const float* Wk     = (const float*)d_in[3];
  const float* bk     = (const float*)d_in[4];
  const float* gk     = (const float*)d_in[5];
  const float* betak  = (const float*)d_in[6];
  const float* Wfc    = (const float*)d_in[7];
  /* bfc = d_in[8] cancels analytically (mean of pos_in == bfc) */
  const float* gfc    = (const float*)d_in[9];
  const float* betafc = (const float*)d_in[10];
  const float* Wt     = (const float*)d_in[11];
  const float* bt     = (const float*)d_in[12];
  const float* gt     = (const float*)d_in[13];
  const float* betat  = (const float*)d_in[14];
  const float* Woff   = (const float*)d_in[15];
  const float* boff   = (const float*)d_in[16];
  const float* Wattn  = (const float*)d_in[17];
  const float* battn  = (const float*)d_in[18];
  const float* Wval   = (const float*)d_in[19];
  const float* bval   = (const float*)d_in[20];
  const float* Wout   = (const float*)d_in[21];
  const float* bout   = (const float*)d_in[22];
  const float* Wf     = (const float*)d_in[23];
  const float* bf     = (const float*)d_in[24];
  const float* gf     = (const float*)d_in[25];
  const float* betaf  = (const float*)d_in[26];
  float* out = (float*)d_out;

  k_init  <<<HWIMG/NT, NT>>>(imf, Wval, bval);
  k_A     <<<NB, NT>>>(pf, grid, Wk, bk);
  k_scan1 <<<SCANB, 512>>>();
  k_scan23<<<SCANB, 512>>>();
  k_C     <<<NB, NT>>>(grid, gk, betak, Wt, bt);
  k_E     <<<NB, NT>>>(grid, Wfc, gfc, betafc, gt, betat,
                       Woff, boff, Wattn, battn, Wout, bout, Wf, bf);
  k_G     <<<NB, NT>>>(gf, betaf, out);
}

// round 5
// speedup vs baseline: 1.9788x; 1.6534x over previous
#include <cuda_runtime.h>

#define NPTS 16384
#define CC 16
#define HH 256
#define WW 704
#define HWIMG (HH*WW)        // 180224
#define EPSBN 1e-3f
#define NB 128
#define NT 128
#define INVN (1.0f/16384.0f)
#define NSX 44               // supercells per row (704/16)
#define NSC (HH*NSX)         // 11264 supercells
#define KNNR 10              // Chebyshev window radius
#define KNNTH 120ULL         // exact if 9th d2 <= (R+1)^2 - 1

// ------------------------- device scratch ----------------------------------
__device__ __align__(16) float g_val[HWIMG*CC];
__device__ __align__(16) float g_imt[HWIMG*CC];
__device__ __align__(16) float g_neigh[NPTS*CC];
__device__ __align__(16) float g_Y1[NPTS*CC];
__device__ __align__(16) float g_pts[NPTS*CC];
__device__ __align__(16) float g_Y3[NPTS*CC];
__device__ __align__(16) float g_Y4[NPTS*CC];
__device__ float g_pA[NB*34];
__device__ float g_p2[NB*37];
__device__ float g_p3[NB*32];
__device__ int g_cellCnt[NSC];
__device__ int g_cellStart[NSC+1];
__device__ unsigned g_packed[NPTS];   // (y<<24)|(x<<14)|idx, grouped by supercell

__device__ __forceinline__ float warpSum(float v){
#pragma unroll
  for(int o=16;o>0;o>>=1) v += __shfl_down_sync(0xffffffffu, v, o);
  return v;
}
__device__ __forceinline__ float warpMax(float v){
#pragma unroll
  for(int o=16;o>0;o>>=1) v = fmaxf(v, __shfl_down_sync(0xffffffffu, v, o));
  return v;
}

// ------------------------- K1: zero counts + value table + imf transpose ----
__global__ void __launch_bounds__(NT) k_init(const float* __restrict__ imf,
                                             const float* __restrict__ Wval,
                                             const float* __restrict__ bval){
  __shared__ float sW[CC*CC];
  __shared__ float sb[CC];
  int t = threadIdx.x;
  for(int i=t;i<CC*CC;i+=NT) sW[i]=Wval[i];
  if(t<CC) sb[t]=bval[t];
  __syncthreads();
  int p = blockIdx.x*NT + t;
  if(p < NSC) g_cellCnt[p] = 0;
  float x[CC];
#pragma unroll
  for(int c=0;c<CC;c++) x[c] = imf[c*HWIMG + p];
  float4* it = (float4*)(g_imt + p*CC);
  it[0] = make_float4(x[0],x[1],x[2],x[3]);
  it[1] = make_float4(x[4],x[5],x[6],x[7]);
  it[2] = make_float4(x[8],x[9],x[10],x[11]);
  it[3] = make_float4(x[12],x[13],x[14],x[15]);
  float o[CC];
#pragma unroll
  for(int j=0;j<CC;j++){
    float s = sb[j];
#pragma unroll
    for(int c=0;c<CC;c++) s += x[c]*sW[c*CC+j];
    o[j]=s;
  }
  float4* dst = (float4*)(g_val + p*CC);
  dst[0] = make_float4(o[0],o[1],o[2],o[3]);
  dst[1] = make_float4(o[4],o[5],o[6],o[7]);
  dst[2] = make_float4(o[8],o[9],o[10],o[11]);
  dst[3] = make_float4(o[12],o[13],o[14],o[15]);
}

// ------------------------- K2: cell count + Y1 = pf@Wk+bk + stats -----------
__global__ void __launch_bounds__(NT) k_A(const float* __restrict__ pf,
                                          const int* __restrict__ grid,
                                          const float* __restrict__ Wk,
                                          const float* __restrict__ bk){
  __shared__ float sW[CC*CC];
  __shared__ float sb[CC];
  __shared__ float red[4][34];
  int t = threadIdx.x;
  for(int i=t;i<CC*CC;i+=NT) sW[i]=Wk[i];
  if(t<CC) sb[t]=bk[t];
  __syncthreads();
  int n = blockIdx.x*NT + t;
  int gyi = grid[2*n], gxi = grid[2*n+1];
  atomicAdd(&g_cellCnt[gyi*NSX + (gxi>>4)], 1);
  float x[CC];
#pragma unroll
  for(int c=0;c<CC;c++) x[c]=pf[n*CC+c];
  float y[CC];
#pragma unroll
  for(int j=0;j<CC;j++){
    float s=sb[j];
#pragma unroll
    for(int c=0;c<CC;c++) s += x[c]*sW[c*CC+j];
    y[j]=s;
    g_Y1[n*CC+j]=s;
  }
  float gy=(float)gyi, gx=(float)gxi;
  int lane=t&31, wid=t>>5;
#pragma unroll
  for(int c=0;c<CC;c++){ float s=warpSum(y[c]);      if(!lane) red[wid][c]=s; }
#pragma unroll
  for(int c=0;c<CC;c++){ float s=warpSum(y[c]*y[c]); if(!lane) red[wid][16+c]=s; }
  { float s=warpSum(gy); if(!lane) red[wid][32]=s; }
  { float s=warpSum(gx); if(!lane) red[wid][33]=s; }
  __syncthreads();
  if(t<34) g_pA[blockIdx.x*34+t] = red[0][t]+red[1][t]+red[2][t]+red[3][t];
}

// ------------------------- K3: single-block scan of 11264 supercell counts --
__global__ void __launch_bounds__(512) k_scan(){
  __shared__ int sh[512];
  int t = threadIdx.x;
  int base = t*22;
  int loc[22];
  int s = 0;
#pragma unroll
  for(int i=0;i<22;i++){ loc[i]=s; s += g_cellCnt[base+i]; }
  sh[t]=s; __syncthreads();
#pragma unroll
  for(int off=1; off<512; off<<=1){
    int x = (t>=off) ? sh[t-off] : 0;
    __syncthreads();
    sh[t] += x;
    __syncthreads();
  }
  int pref = sh[t] - s;   // exclusive prefix of this chunk
#pragma unroll
  for(int i=0;i<22;i++) g_cellStart[base+i] = pref + loc[i];
  if(t==511) g_cellStart[NSC] = NPTS;
}

// ------------------------- K4: scatter packed points + stage C --------------
__global__ void __launch_bounds__(NT) k_C(const int* __restrict__ grid,
                                          const float* __restrict__ gk,
                                          const float* __restrict__ betak,
                                          const float* __restrict__ Wt,
                                          const float* __restrict__ bt){
  __shared__ float sA[34];
  __shared__ float sa1[CC], sb1[CC], scc[2];
  __shared__ float sW[CC*CC], sbt[CC];
  __shared__ float red[4][37];
  int t = threadIdx.x;
  for(int i=t;i<CC*CC;i+=NT) sW[i]=Wt[i];
  if(t<CC) sbt[t]=bt[t];
  if(t<34){ float s=0.f; for(int e=0;e<NB;e++) s+=g_pA[e*34+t]; sA[t]=s; }
  __syncthreads();
  if(t<CC){
    float m = sA[t]*INVN;
    float v = sA[16+t]*INVN - m*m;
    float is = rsqrtf(v+EPSBN);
    sa1[t] = is*gk[t];
    sb1[t] = betak[t] - m*is*gk[t];
  }
  if(t==16) scc[0]=sA[32]*INVN;
  if(t==17) scc[1]=sA[33]*INVN;
  __syncthreads();
  int n = blockIdx.x*NT + t;
  int gyi = grid[2*n], gxi = grid[2*n+1];
  {
    int cid = gyi*NSX + (gxi>>4);
    int old = atomicSub(&g_cellCnt[cid], 1);
    g_packed[g_cellStart[cid] + old - 1] =
        ((unsigned)gyi<<24) | ((unsigned)gxi<<14) | (unsigned)n;
  }
  float p[CC];
#pragma unroll
  for(int c=0;c<CC;c++){
    float v = g_Y1[n*CC+c]*sa1[c] + sb1[c];
    p[c]=v;
    g_pts[n*CC+c]=v;
  }
  float y3[CC];
#pragma unroll
  for(int j=0;j<CC;j++){
    float s=sbt[j];
#pragma unroll
    for(int c=0;c<CC;c++) s += p[c]*sW[c*CC+j];
    y3[j]=s;
    g_Y3[n*CC+j]=s;
  }
  float ry=(float)gyi-scc[0], rx=(float)gxi-scc[1];
  int lane=t&31, wid=t>>5;
#pragma unroll
  for(int c=0;c<CC;c++){ float s=warpSum(y3[c]);        if(!lane) red[wid][c]=s; }
#pragma unroll
  for(int c=0;c<CC;c++){ float s=warpSum(y3[c]*y3[c]);  if(!lane) red[wid][16+c]=s; }
  { float s=warpSum(ry*ry); if(!lane) red[wid][32]=s; }
  { float s=warpSum(rx*rx); if(!lane) red[wid][33]=s; }
  { float s=warpSum(ry*rx); if(!lane) red[wid][34]=s; }
  { float s=warpMax(fabsf(ry)); if(!lane) red[wid][35]=s; }
  { float s=warpMax(fabsf(rx)); if(!lane) red[wid][36]=s; }
  __syncthreads();
  if(t<35)      g_p2[blockIdx.x*37+t] = red[0][t]+red[1][t]+red[2][t]+red[3][t];
  else if(t<37) g_p2[blockIdx.x*37+t] = fmaxf(fmaxf(red[0][t],red[1][t]),fmaxf(red[2][t],red[3][t]));
}

// ------------------------- KNN helpers --------------------------------------
__device__ __forceinline__ unsigned long long umin64(unsigned long long a, unsigned long long b){
  return a<b ? a : b;
}
__device__ __forceinline__ unsigned long long umax64(unsigned long long a, unsigned long long b){
  return a<b ? b : a;
}
#define INS9(L0,L1,L2,L3,L4,L5,L6,L7,L8,KEY) do{ \
  unsigned long long _k=(KEY); \
  if(_k < L8){ \
    unsigned long long _t; \
    _t=L0; L0=umin64(_t,_k); _k=umax64(_t,_k); \
    _t=L1; L1=umin64(_t,_k); _k=umax64(_t,_k); \
    _t=L2; L2=umin64(_t,_k); _k=umax64(_t,_k); \
    _t=L3; L3=umin64(_t,_k); _k=umax64(_t,_k); \
    _t=L4; L4=umin64(_t,_k); _k=umax64(_t,_k); \
    _t=L5; L5=umin64(_t,_k); _k=umax64(_t,_k); \
    _t=L6; L6=umin64(_t,_k); _k=umax64(_t,_k); \
    _t=L7; L7=umin64(_t,_k); _k=umax64(_t,_k); \
    L8=umin64(L8,_k); \
  } }while(0)

__device__ __forceinline__ int isqrt_dev(int v){
  if(v < 0) return -1;
  int h = (int)sqrtf((float)v);
  while((h+1)*(h+1) <= v) h++;
  while(h>0 && h*h > v) h--;
  return h;
}

// ------------------------- K5: warp-per-query KNN + neighbor mean -----------
__global__ void __launch_bounds__(128) k_knn(const int* __restrict__ grid){
  const unsigned FULL = 0xffffffffu;
  int lane = threadIdx.x & 31;
  int n = blockIdx.x*4 + (threadIdx.x >> 5);
  int qy = __ldg(&grid[2*n]), qx = __ldg(&grid[2*n+1]);

  unsigned long long l0=~0ULL,l1=~0ULL,l2=~0ULL,l3=~0ULL,l4=~0ULL,
                     l5=~0ULL,l6=~0ULL,l7=~0ULL,l8=~0ULL;
  // lane-parallel row scan over Chebyshev window
  int row = qy - KNNR + lane;
  int s=0, e=0;
  if(lane < 2*KNNR+1 && row >= 0 && row < HH){
    int sxlo = max(qx-KNNR,0) >> 4;
    int sxhi = min(qx+KNNR,WW-1) >> 4;
    s = g_cellStart[row*NSX + sxlo];
    e = g_cellStart[row*NSX + sxhi + 1];
  }
  while(__any_sync(FULL, s<e)){
    if(s<e){
      unsigned p = g_packed[s]; s++;
      int dy = (int)(p>>24) - qy;
      int dx = (int)((p>>14)&0x3FFu) - qx;
      unsigned long long key =
        ((unsigned long long)(unsigned)(dy*dy+dx*dx) << 14) | (p & 0x3FFFu);
      INS9(l0,l1,l2,l3,l4,l5,l6,l7,l8,key);
    }
  }
  // 9-round warp merge
  unsigned long long w0,w1,w2,w3,w4,w5,w6,w7,w8;
#define ROUND(WR) { \
    unsigned long long m=l0; \
    _Pragma("unroll") \
    for(int o=16;o>0;o>>=1){ unsigned long long t2=__shfl_xor_sync(FULL,m,o); if(t2<m)m=t2; } \
    WR = m; \
    if(l0==m){ l0=l1;l1=l2;l2=l3;l3=l4;l4=l5;l5=l6;l6=l7;l7=l8;l8=~0ULL; } }
  ROUND(w0) ROUND(w1) ROUND(w2) ROUND(w3) ROUND(w4)
  ROUND(w5) ROUND(w6) ROUND(w7) ROUND(w8)
#undef ROUND

  // exactness check; rare scalar fallback on lane 0 (exact, adaptive rows)
  if(w8 == ~0ULL || (w8>>14) > KNNTH){
    unsigned long long f0=~0ULL,f1=~0ULL,f2=~0ULL,f3=~0ULL,f4=~0ULL,
                       f5=~0ULL,f6=~0ULL,f7=~0ULL,f8=~0ULL;
    if(lane==0){
      for(int d=0; d<HH; d++){
        if(f8 != ~0ULL && (unsigned long long)(d*d) > (f8>>14)) break;
        for(int sgn=0; sgn<2; sgn++){
          if(d==0 && sgn) break;
          int y = sgn ? qy+d : qy-d;
          if((unsigned)y >= HH) continue;
          int xlo=0, xhi=WW-1;
          if(f8 != ~0ULL){
            int v = (int)(f8>>14) - d*d;
            if(v < 0) continue;
            int hw = isqrt_dev(v);
            xlo = max(qx-hw,0); xhi = min(qx+hw,WW-1);
          }
          int ss = g_cellStart[y*NSX + (xlo>>4)];
          int ee = g_cellStart[y*NSX + (xhi>>4) + 1];
          for(; ss<ee; ss++){
            unsigned p = g_packed[ss];
            int dy = (int)(p>>24) - qy;
            int dx = (int)((p>>14)&0x3FFu) - qx;
            unsigned long long key =
              ((unsigned long long)(unsigned)(dy*dy+dx*dx) << 14) | (p & 0x3FFFu);
            INS9(f0,f1,f2,f3,f4,f5,f6,f7,f8,key);
          }
        }
      }
    }
    w0=__shfl_sync(FULL,f0,0); w1=__shfl_sync(FULL,f1,0); w2=__shfl_sync(FULL,f2,0);
    w3=__shfl_sync(FULL,f3,0); w4=__shfl_sync(FULL,f4,0); w5=__shfl_sync(FULL,f5,0);
    w6=__shfl_sync(FULL,f6,0); w7=__shfl_sync(FULL,f7,0); w8=__shfl_sync(FULL,f8,0);
  }

  // neighbor-mean over winners 1..8 (winner 0 = lexicographic min, dropped)
  // offsets (broadcast loads, every lane computes all 8)
  int j1=(int)(w1&0x3FFFULL), j2=(int)(w2&0x3FFFULL), j3=(int)(w3&0x3FFFULL),
      j4=(int)(w4&0x3FFFULL), j5=(int)(w5&0x3FFFULL), j6=(int)(w6&0x3FFFULL),
      j7=(int)(w7&0x3FFFULL), j8=(int)(w8&0x3FFFULL);
  int o1=__ldg(&grid[2*j1])*WW+__ldg(&grid[2*j1+1]);
  int o2=__ldg(&grid[2*j2])*WW+__ldg(&grid[2*j2+1]);
  int o3=__ldg(&grid[2*j3])*WW+__ldg(&grid[2*j3+1]);
  int o4=__ldg(&grid[2*j4])*WW+__ldg(&grid[2*j4+1]);
  int o5=__ldg(&grid[2*j5])*WW+__ldg(&grid[2*j5+1]);
  int o6=__ldg(&grid[2*j6])*WW+__ldg(&grid[2*j6+1]);
  int o7=__ldg(&grid[2*j7])*WW+__ldg(&grid[2*j7+1]);
  int o8=__ldg(&grid[2*j8])*WW+__ldg(&grid[2*j8+1]);
  int ni = lane>>2;                 // neighbor group 0..7 -> winner ni+1
  int off = o1;
  off = (ni==1)?o2:off; off = (ni==2)?o3:off; off = (ni==3)?o4:off;
  off = (ni==4)?o5:off; off = (ni==5)?o6:off; off = (ni==6)?o7:off;
  off = (ni==7)?o8:off;
  float4 v = *(const float4*)(g_imt + off*CC + (lane&3)*4);
#pragma unroll
  for(int o=4;o<=16;o<<=1){
    v.x += __shfl_xor_sync(FULL, v.x, o);
    v.y += __shfl_xor_sync(FULL, v.y, o);
    v.z += __shfl_xor_sync(FULL, v.z, o);
    v.w += __shfl_xor_sync(FULL, v.w, o);
  }
  if(lane < 4){
    v.x*=0.125f; v.y*=0.125f; v.z*=0.125f; v.w*=0.125f;
    ((float4*)(g_neigh + n*CC))[lane] = v;
  }
}

// ------------------------- K6: deform attn + fuse + Y4 stats ----------------
__global__ void __launch_bounds__(NT) k_E(const int* __restrict__ grid,
    const float* __restrict__ Wfc, const float* __restrict__ gfc, const float* __restrict__ betafc,
    const float* __restrict__ gt,  const float* __restrict__ betat,
    const float* __restrict__ Woff,const float* __restrict__ boff,
    const float* __restrict__ Wattn,const float* __restrict__ battn,
    const float* __restrict__ Wout,const float* __restrict__ bout,
    const float* __restrict__ Wf,  const float* __restrict__ bf){
  __shared__ float sF[40];
  __shared__ float sWoff[CC*32], sWattn[CC*16], sWout[CC*16], sWf[32*CC];
  __shared__ float sboff[32], sbattn[16], sbout[16], sbf[16];
  __shared__ float sa3[16], sb3[16], su0[16], su1[16], sb2[16], sc[2];
  __shared__ float red[4][32];
  int t = threadIdx.x;
  for(int i=t;i<CC*32;i+=NT) sWoff[i]=Woff[i];
  for(int i=t;i<CC*16;i+=NT){ sWattn[i]=Wattn[i]; sWout[i]=Wout[i]; }
  for(int i=t;i<32*CC;i+=NT) sWf[i]=Wf[i];
  if(t<32) sboff[t]=boff[t];
  if(t<16){ sbattn[t]=battn[t]; sbout[t]=bout[t]; sbf[t]=bf[t]; }
  if(t<35){ float s=0.f; for(int e=0;e<NB;e++) s+=g_p2[e*37+t]; sF[t]=s; }
  else if(t<37){ float m=0.f; for(int e=0;e<NB;e++) m=fmaxf(m,g_p2[e*37+t]); sF[t]=m; }
  else if(t<39){ float s=0.f; for(int e=0;e<NB;e++) s+=g_pA[e*34+32+(t-37)]; sF[t]=s; }
  __syncthreads();
  if(t<16){
    float m3 = sF[t]*INVN;
    float v3 = sF[16+t]*INVN - m3*m3;
    float is3 = rsqrtf(v3+EPSBN);
    sa3[t] = is3*gt[t];
    sb3[t] = betat[t] - m3*is3*gt[t];
    float mxy = sF[35]; if(mxy==0.f) mxy=1.f;
    float mxx = sF[36]; if(mxx==0.f) mxx=1.f;
    float Syy=sF[32]*INVN, Sxx=sF[33]*INVN, Sxy=sF[34]*INVN;
    float w0 = Wfc[t]/mxy;
    float w1 = Wfc[16+t]/mxx;
    float v2 = w0*w0*Syy + 2.f*w0*w1*Sxy + w1*w1*Sxx;
    float a2 = rsqrtf(v2+EPSBN)*gfc[t];
    su0[t]=w0*a2; su1[t]=w1*a2; sb2[t]=betafc[t];
  }
  if(t==16){ sc[0]=sF[37]*INVN; sc[1]=sF[38]*INVN; }
  __syncthreads();

  int n = blockIdx.x*NT + t;
  int qyi = grid[2*n], qxi = grid[2*n+1];
  float gy=(float)qyi, gx=(float)qxi;
  float ry=gy-sc[0], rx=gx-sc[1];
  float q[16];
#pragma unroll
  for(int c=0;c<16;c++)
    q[c] = g_pts[n*CC+c] + ry*su0[c] + rx*su1[c] + sb2[c];

  float a[16];
#pragma unroll
  for(int hp=0;hp<16;hp++){
    float l=sbattn[hp];
#pragma unroll
    for(int c=0;c<16;c++) l += q[c]*sWattn[c*16+hp];
    a[hp]=l;
  }
#pragma unroll
  for(int h=0;h<4;h++){
    float m=fmaxf(fmaxf(a[4*h],a[4*h+1]),fmaxf(a[4*h+2],a[4*h+3]));
    float e0=expf(a[4*h]-m), e1=expf(a[4*h+1]-m), e2=expf(a[4*h+2]-m), e3=expf(a[4*h+3]-m);
    float inv=1.f/(e0+e1+e2+e3);
    a[4*h]=e0*inv; a[4*h+1]=e1*inv; a[4*h+2]=e2*inv; a[4*h+3]=e3*inv;
  }

  float acc[16];
#pragma unroll
  for(int c=0;c<16;c++) acc[c]=0.f;

#define CORNER(Yf,Xf,Wgt) do{ \
    float _y=(Yf), _x=(Xf); \
    if(_y>=0.f && _y<=(float)(HH-1) && _x>=0.f && _x<=(float)(WW-1)){ \
      int _i = ((int)_y)*WW + (int)_x; \
      const float4 _v = *(const float4*)(g_val + _i*CC + h*4); \
      float _w=(Wgt); \
      acc[h*4+0]+=_w*_v.x; acc[h*4+1]+=_w*_v.y; acc[h*4+2]+=_w*_v.z; acc[h*4+3]+=_w*_v.w; \
    } }while(0)

#pragma unroll
  for(int h=0;h<4;h++){
#pragma unroll
    for(int p=0;p<4;p++){
      float offy=sboff[h*8+p*2], offx=sboff[h*8+p*2+1];
#pragma unroll
      for(int c=0;c<16;c++){
        offy += q[c]*sWoff[c*32 + h*8+p*2];
        offx += q[c]*sWoff[c*32 + h*8+p*2+1];
      }
      float ly=gy+offy, lx=gx+offx;
      float fy=floorf(ly), fx=floorf(lx);
      float wy=ly-fy, wx=lx-fx;
      float ap=a[h*4+p];
      CORNER(fy,     fx,     ap*(1.f-wy)*(1.f-wx));
      CORNER(fy,     fx+1.f, ap*(1.f-wy)*wx);
      CORNER(fy+1.f, fx,     ap*wy*(1.f-wx));
      CORNER(fy+1.f, fx+1.f, ap*wy*wx);
    }
  }
#undef CORNER

  const float* nb = g_neigh + n*CC;
  float img[16];
#pragma unroll
  for(int c=0;c<16;c++){
    float s=sbout[c];
#pragma unroll
    for(int k=0;k<16;k++) s += acc[k]*sWout[k*16+c];
    img[c] = s + nb[c];
  }
  float pp[16];
#pragma unroll
  for(int c=0;c<16;c++) pp[c] = g_Y3[n*CC+c]*sa3[c] + sb3[c];

  float y4[16];
#pragma unroll
  for(int c=0;c<16;c++){
    float s=sbf[c];
#pragma unroll
    for(int k=0;k<16;k++) s += fmaxf(pp[k],0.f)*sWf[k*16+c];
#pragma unroll
    for(int k=0;k<16;k++) s += fmaxf(img[k],0.f)*sWf[(16+k)*16+c];
    y4[c]=s;
    g_Y4[n*CC+c]=s;
  }
  int lane=t&31, wid=t>>5;
#pragma unroll
  for(int c=0;c<16;c++){ float s=warpSum(y4[c]);        if(!lane) red[wid][c]=s; }
#pragma unroll
  for(int c=0;c<16;c++){ float s=warpSum(y4[c]*y4[c]);  if(!lane) red[wid][16+c]=s; }
  __syncthreads();
  if(t<32) g_p3[blockIdx.x*32+t] = red[0][t]+red[1][t]+red[2][t]+red[3][t];
}

// ------------------------- K7: final BN + relu -> d_out ---------------------
__global__ void __launch_bounds__(NT) k_G(const float* __restrict__ gf,
                                          const float* __restrict__ betaf,
                                          float* __restrict__ out){
  __shared__ float sP[32];
  __shared__ float a4[16], b4[16];
  int t = threadIdx.x;
  if(t<32){ float s=0.f; for(int e=0;e<NB;e++) s+=g_p3[e*32+t]; sP[t]=s; }
  __syncthreads();
  if(t<16){
    float m = sP[t]*INVN;
    float v = sP[16+t]*INVN - m*m;
    float is = rsqrtf(v+EPSBN);
    a4[t]=is*gf[t];
    b4[t]=betaf[t] - m*is*gf[t];
  }
  __syncthreads();
  int n = blockIdx.x*NT + t;
#pragma unroll
  for(int c=0;c<16;c++)
    out[n*CC+c] = fmaxf(g_Y4[n*CC+c]*a4[c] + b4[c], 0.f);
}

// ------------------------- launch ------------------------------------------
extern "C" void kernel_launch(void* const* d_in, const int* in_sizes, int n_in,
                              void* d_out, int out_size){
  const float* pf     = (const float*)d_in[0];
  const float* imf    = (const float*)d_in[1];
  const int*   grid   = (const int*)  d_in[2];
  const float* Wk     = (const float*)d_in[3];
  const float* bk     = (const float*)d_in[4];
  const float* gk     = (const float*)d_in[5];
  const float* betak  = (const float*)d_in[6];
  const float* Wfc    = (const float*)d_in[7];
  /* bfc = d_in[8] cancels analytically */
  const float* gfc    = (const float*)d_in[9];
  const float* betafc = (const float*)d_in[10];
  const float* Wt     = (const float*)d_in[11];
  const float* bt     = (const float*)d_in[12];
  const float* gt     = (const float*)d_in[13];
  const float* betat  = (const float*)d_in[14];
  const float* Woff   = (const float*)d_in[15];
  const float* boff   = (const float*)d_in[16];
  const float* Wattn  = (const float*)d_in[17];
  const float* battn  = (const float*)d_in[18];
  const float* Wval   = (const float*)d_in[19];
  const float* bval   = (const float*)d_in[20];
  const float* Wout   = (const float*)d_in[21];
  const float* bout   = (const float*)d_in[22];
  const float* Wf     = (const float*)d_in[23];
  const float* bf     = (const float*)d_in[24];
  const float* gf     = (const float*)d_in[25];
  const float* betaf  = (const float*)d_in[26];
  float* out = (float*)d_out;

  k_init <<<HWIMG/NT, NT>>>(imf, Wval, bval);
  k_A    <<<NB, NT>>>(pf, grid, Wk, bk);
  k_scan <<<1, 512>>>();
  k_C    <<<NB, NT>>>(grid, gk, betak, Wt, bt);
  k_knn  <<<NPTS/4, 128>>>(grid);
  k_E    <<<NB, NT>>>(grid, Wfc, gfc, betafc, gt, betat,
                      Woff, boff, Wattn, battn, Wout, bout, Wf, bf);
  k_G    <<<NB, NT>>>(gf, betaf, out);
}

// round 6
// speedup vs baseline: 2.0544x; 1.0382x over previous
#include <cuda_runtime.h>

#define NPTS 16384
#define CC 16
#define HH 256
#define WW 704
#define HWIMG (HH*WW)        // 180224
#define EPSBN 1e-3f
#define NB 128
#define NT 128
#define INVN (1.0f/16384.0f)
#define NSX 44               // supercells per row (704/16)
#define NSC (HH*NSX)         // 11264 = 128*88
#define CHUNK 88             // supercells per k_SS block
#define KNNR 10
#define KNNTH 120ULL

// ------------------------- device scratch ----------------------------------
__device__ __align__(16) float g_val[HWIMG*CC];
__device__ __align__(16) float g_imt[HWIMG*CC];
__device__ __align__(16) float g_neigh[NPTS*CC];
__device__ __align__(16) float g_pts[NPTS*CC];
__device__ __align__(16) float g_Y3[NPTS*CC];
__device__ float g_pA[34*NB];        // transposed: [item][block]
__device__ float g_p2[37*NB];
__device__ float g_p3[32*NB];
__device__ int g_cellCnt[NSC];       // zero-init; self-zeroing (scatter drains)
__device__ int g_cellStart[NSC+1];
__device__ int g_bs[NB];
__device__ unsigned g_packed[NPTS];  // (idx<<18)|(y<<10)|x, grouped by supercell
__device__ int g_bc[4];              // phase barrier counters (self-resetting)

__device__ __forceinline__ float warpSum(float v){
#pragma unroll
  for(int o=16;o>0;o>>=1) v += __shfl_down_sync(0xffffffffu, v, o);
  return v;
}
__device__ __forceinline__ int warpSumI(int v){
#pragma unroll
  for(int o=16;o>0;o>>=1) v += __shfl_down_sync(0xffffffffu, v, o);
  return v;
}
__device__ __forceinline__ float warpMax(float v){
#pragma unroll
  for(int o=16;o>0;o>>=1) v = fmaxf(v, __shfl_down_sync(0xffffffffu, v, o));
  return v;
}

// grid barrier across NB resident blocks; counter idx, target NB
__device__ __forceinline__ void gbar(int idx){
  __syncthreads();
  if(threadIdx.x==0){
    __threadfence();
    atomicAdd(&g_bc[idx], 1);
    while(((volatile int*)g_bc)[idx] < NB) __nanosleep(32);
    __threadfence();
  }
  __syncthreads();
}

// ------------------------- K1: value table + imf transpose ------------------
__global__ void __launch_bounds__(NT) k_init(const float* __restrict__ imf,
                                             const float* __restrict__ Wval,
                                             const float* __restrict__ bval){
  __shared__ float sW[CC*CC];
  __shared__ float sb[CC];
  int t = threadIdx.x;
  for(int i=t;i<CC*CC;i+=NT) sW[i]=Wval[i];
  if(t<CC) sb[t]=bval[t];
  __syncthreads();
  int p = blockIdx.x*NT + t;
  float x[CC];
#pragma unroll
  for(int c=0;c<CC;c++) x[c] = imf[c*HWIMG + p];
  float4* it = (float4*)(g_imt + p*CC);
  it[0] = make_float4(x[0],x[1],x[2],x[3]);
  it[1] = make_float4(x[4],x[5],x[6],x[7]);
  it[2] = make_float4(x[8],x[9],x[10],x[11]);
  it[3] = make_float4(x[12],x[13],x[14],x[15]);
  float o[CC];
#pragma unroll
  for(int j=0;j<CC;j++){
    float s = sb[j];
#pragma unroll
    for(int c=0;c<CC;c++) s += x[c]*sW[c*CC+j];
    o[j]=s;
  }
  float4* dst = (float4*)(g_val + p*CC);
  dst[0] = make_float4(o[0],o[1],o[2],o[3]);
  dst[1] = make_float4(o[4],o[5],o[6],o[7]);
  dst[2] = make_float4(o[8],o[9],o[10],o[11]);
  dst[3] = make_float4(o[12],o[13],o[14],o[15]);
}

// ------------------------- K2: persistent A + scan + scatter + C ------------
__global__ void __launch_bounds__(NT) k_SS(const float* __restrict__ pf,
    const int* __restrict__ grid,
    const float* __restrict__ Wk, const float* __restrict__ bk,
    const float* __restrict__ gk, const float* __restrict__ betak,
    const float* __restrict__ Wt, const float* __restrict__ bt){
  __shared__ float sW[CC*CC];
  __shared__ float sb[CC];
  __shared__ float red[4][37];
  __shared__ int shi[NT];
  __shared__ int sred[4];
  __shared__ float sA[34];
  __shared__ float sa1[CC], sb1[CC], scc[2];
  int b=blockIdx.x, t=threadIdx.x;
  int lane=t&31, w=t>>5;
  if(b==0 && t==0) *(volatile int*)&g_bc[3] = 0;   // reset EG barrier for this replay

  // ---- P0: count + Y1 (kept in registers) + partials ----
  for(int i=t;i<CC*CC;i+=NT) sW[i]=Wk[i];
  if(t<CC) sb[t]=bk[t];
  __syncthreads();
  int n = b*NT + t;
  int gyi = grid[2*n], gxi = grid[2*n+1];
  atomicAdd(&g_cellCnt[gyi*NSX + (gxi>>4)], 1);
  float x[CC], y[CC];
#pragma unroll
  for(int c=0;c<CC;c++) x[c]=pf[n*CC+c];
#pragma unroll
  for(int j=0;j<CC;j++){
    float s=sb[j];
#pragma unroll
    for(int c=0;c<CC;c++) s += x[c]*sW[c*CC+j];
    y[j]=s;
  }
#pragma unroll
  for(int c=0;c<CC;c++){ float s=warpSum(y[c]);      if(!lane) red[w][c]=s; }
#pragma unroll
  for(int c=0;c<CC;c++){ float s=warpSum(y[c]*y[c]); if(!lane) red[w][16+c]=s; }
  { float s=warpSum((float)gyi); if(!lane) red[w][32]=s; }
  { float s=warpSum((float)gxi); if(!lane) red[w][33]=s; }
  __syncthreads();
  if(t<34) g_pA[t*NB+b] = red[0][t]+red[1][t]+red[2][t]+red[3][t];
  gbar(0);

  // ---- P1: per-block chunk scan of 88 supercell counts ----
  int cbase = b*CHUNK;
  int v = (t<CHUNK) ? g_cellCnt[cbase+t] : 0;
  shi[t]=v; __syncthreads();
#pragma unroll
  for(int off=1; off<NT; off<<=1){
    int xx = (t>=off) ? shi[t-off] : 0;
    __syncthreads();
    shi[t] += xx;
    __syncthreads();
  }
  if(t<CHUNK) g_cellStart[cbase+t] = shi[t]-v;
  if(t==NT-1) g_bs[b] = shi[NT-1];
  gbar(1);

  // ---- P2: add block offsets ----
  {
    int vb = (t<b) ? g_bs[t] : 0;
    int s = warpSumI(vb);
    if(!lane) sred[w]=s;
    __syncthreads();
    int off = sred[0]+sred[1]+sred[2]+sred[3];
    if(t<CHUNK) g_cellStart[cbase+t] += off;
    if(b==0 && t==0) g_cellStart[NSC]=NPTS;
  }
  gbar(2);

  // ---- P3: stats finalize + scatter + pts/Y3 + p2 partials ----
  for(int i=w;i<34;i+=4){
    const float* pp = g_pA + i*NB;
    float s = pp[lane]+pp[lane+32]+pp[lane+64]+pp[lane+96];
    s = warpSum(s);
    if(!lane) sA[i]=s;
  }
  for(int i=t;i<CC*CC;i+=NT) sW[i]=Wt[i];
  if(t<CC) sb[t]=bt[t];
  __syncthreads();
  if(t<CC){
    float m = sA[t]*INVN;
    float vv = sA[16+t]*INVN - m*m;
    float is = rsqrtf(vv+EPSBN);
    sa1[t] = is*gk[t];
    sb1[t] = betak[t] - m*is*gk[t];
  }
  if(t==16) scc[0]=sA[32]*INVN;
  if(t==17) scc[1]=sA[33]*INVN;
  __syncthreads();
  {
    int cid = gyi*NSX + (gxi>>4);
    int old = atomicSub(&g_cellCnt[cid], 1);   // drains back to 0 (replay-safe)
    g_packed[g_cellStart[cid] + old - 1] =
        ((unsigned)n<<18) | ((unsigned)gyi<<10) | (unsigned)gxi;
  }
  float p[CC];
#pragma unroll
  for(int c=0;c<CC;c++){
    float vv = y[c]*sa1[c] + sb1[c];
    p[c]=vv;
    g_pts[n*CC+c]=vv;
  }
  float y3[CC];
#pragma unroll
  for(int j=0;j<CC;j++){
    float s=sb[j];
#pragma unroll
    for(int c=0;c<CC;c++) s += p[c]*sW[c*CC+j];
    y3[j]=s;
    g_Y3[n*CC+j]=s;
  }
  float ry=(float)gyi-scc[0], rx=(float)gxi-scc[1];
#pragma unroll
  for(int c=0;c<CC;c++){ float s=warpSum(y3[c]);        if(!lane) red[w][c]=s; }
#pragma unroll
  for(int c=0;c<CC;c++){ float s=warpSum(y3[c]*y3[c]);  if(!lane) red[w][16+c]=s; }
  { float s=warpSum(ry*ry); if(!lane) red[w][32]=s; }
  { float s=warpSum(rx*rx); if(!lane) red[w][33]=s; }
  { float s=warpSum(ry*rx); if(!lane) red[w][34]=s; }
  { float s=warpMax(fabsf(ry)); if(!lane) red[w][35]=s; }
  { float s=warpMax(fabsf(rx)); if(!lane) red[w][36]=s; }
  __syncthreads();
  if(t<35)      g_p2[t*NB+b] = red[0][t]+red[1][t]+red[2][t]+red[3][t];
  else if(t<37) g_p2[t*NB+b] = fmaxf(fmaxf(red[0][t],red[1][t]),fmaxf(red[2][t],red[3][t]));
}

// ------------------------- KNN helpers --------------------------------------
__device__ __forceinline__ unsigned long long umin64(unsigned long long a, unsigned long long b){
  return a<b ? a : b;
}
__device__ __forceinline__ unsigned long long umax64(unsigned long long a, unsigned long long b){
  return a<b ? b : a;
}
#define INS9(L0,L1,L2,L3,L4,L5,L6,L7,L8,KEY) do{ \
  unsigned long long _k=(KEY); \
  if(_k < L8){ \
    unsigned long long _t; \
    _t=L0; L0=umin64(_t,_k); _k=umax64(_t,_k); \
    _t=L1; L1=umin64(_t,_k); _k=umax64(_t,_k); \
    _t=L2; L2=umin64(_t,_k); _k=umax64(_t,_k); \
    _t=L3; L3=umin64(_t,_k); _k=umax64(_t,_k); \
    _t=L4; L4=umin64(_t,_k); _k=umax64(_t,_k); \
    _t=L5; L5=umin64(_t,_k); _k=umax64(_t,_k); \
    _t=L6; L6=umin64(_t,_k); _k=umax64(_t,_k); \
    _t=L7; L7=umin64(_t,_k); _k=umax64(_t,_k); \
    L8=umin64(L8,_k); \
  } }while(0)

__device__ __forceinline__ int isqrt_dev(int v){
  if(v < 0) return -1;
  int h = (int)sqrtf((float)v);
  while((h+1)*(h+1) <= v) h++;
  while(h>0 && h*h > v) h--;
  return h;
}

// key = (d2<<32) | (idx<<18) | (y<<10) | x : orders by (d2, idx); carries y,x
__device__ __forceinline__ unsigned long long mkkey(unsigned p, int qy, int qx){
  int dy = (int)((p>>10)&0xFFu) - qy;
  int dx = (int)(p&0x3FFu) - qx;
  return ((unsigned long long)(unsigned)(dy*dy+dx*dx) << 32) | p;
}

// ------------------------- K3: warp-per-query KNN + neighbor mean -----------
__global__ void __launch_bounds__(128) k_knn(const int* __restrict__ grid){
  const unsigned FULL = 0xffffffffu;
  int lane = threadIdx.x & 31;
  int n = blockIdx.x*4 + (threadIdx.x >> 5);
  int qy = __ldg(&grid[2*n]), qx = __ldg(&grid[2*n+1]);

  unsigned long long l0=~0ULL,l1=~0ULL,l2=~0ULL,l3=~0ULL,l4=~0ULL,
                     l5=~0ULL,l6=~0ULL,l7=~0ULL,l8=~0ULL;
  int row = qy - KNNR + lane;
  int s=0, e=0;
  if(lane < 2*KNNR+1 && row >= 0 && row < HH){
    int sxlo = max(qx-KNNR,0) >> 4;
    int sxhi = min(qx+KNNR,WW-1) >> 4;
    s = g_cellStart[row*NSX + sxlo];
    e = g_cellStart[row*NSX + sxhi + 1];
  }
  while(__any_sync(FULL, s<e)){
    if(s<e){
      unsigned p = g_packed[s]; s++;
      unsigned long long key = mkkey(p, qy, qx);
      INS9(l0,l1,l2,l3,l4,l5,l6,l7,l8,key);
    }
  }
  unsigned long long w0,w1,w2,w3,w4,w5,w6,w7,w8;
#define ROUND(WR) { \
    unsigned long long m=l0; \
    _Pragma("unroll") \
    for(int o=16;o>0;o>>=1){ unsigned long long t2=__shfl_xor_sync(FULL,m,o); if(t2<m)m=t2; } \
    WR = m; \
    if(l0==m){ l0=l1;l1=l2;l2=l3;l3=l4;l4=l5;l5=l6;l6=l7;l7=l8;l8=~0ULL; } }
  ROUND(w0) ROUND(w1) ROUND(w2) ROUND(w3) ROUND(w4)
  ROUND(w5) ROUND(w6) ROUND(w7) ROUND(w8)
#undef ROUND

  if(w8 == ~0ULL || (w8>>32) > KNNTH){
    unsigned long long f0=~0ULL,f1=~0ULL,f2=~0ULL,f3=~0ULL,f4=~0ULL,
                       f5=~0ULL,f6=~0ULL,f7=~0ULL,f8=~0ULL;
    if(lane==0){
      for(int d=0; d<HH; d++){
        if(f8 != ~0ULL && (unsigned long long)(d*d) > (f8>>32)) break;
        for(int sgn=0; sgn<2; sgn++){
          if(d==0 && sgn) break;
          int yy = sgn ? qy+d : qy-d;
          if((unsigned)yy >= HH) continue;
          int xlo=0, xhi=WW-1;
          if(f8 != ~0ULL){
            int vv = (int)(f8>>32) - d*d;
            if(vv < 0) continue;
            int hw = isqrt_dev(vv);
            xlo = max(qx-hw,0); xhi = min(qx+hw,WW-1);
          }
          int ss = g_cellStart[yy*NSX + (xlo>>4)];
          int ee = g_cellStart[yy*NSX + (xhi>>4) + 1];
          for(; ss<ee; ss++){
            unsigned long long key = mkkey(g_packed[ss], qy, qx);
            INS9(f0,f1,f2,f3,f4,f5,f6,f7,f8,key);
          }
        }
      }
    }
    w1=__shfl_sync(FULL,f1,0); w2=__shfl_sync(FULL,f2,0);
    w3=__shfl_sync(FULL,f3,0); w4=__shfl_sync(FULL,f4,0); w5=__shfl_sync(FULL,f5,0);
    w6=__shfl_sync(FULL,f6,0); w7=__shfl_sync(FULL,f7,0); w8=__shfl_sync(FULL,f8,0);
  }

  // neighbor-mean over winners 1..8 (winner 0 = lexicographic min, dropped)
  unsigned p1=(unsigned)w1, p2=(unsigned)w2, p3=(unsigned)w3, p4=(unsigned)w4,
           p5=(unsigned)w5, p6=(unsigned)w6, p7=(unsigned)w7, p8=(unsigned)w8;
#define POS(P) ((int)(((P)>>10)&0xFFu)*WW + (int)((P)&0x3FFu))
  int o1=POS(p1),o2=POS(p2),o3=POS(p3),o4=POS(p4),
      o5=POS(p5),o6=POS(p6),o7=POS(p7),o8=POS(p8);
#undef POS
  int ni = lane>>2;
  int off = o1;
  off = (ni==1)?o2:off; off = (ni==2)?o3:off; off = (ni==3)?o4:off;
  off = (ni==4)?o5:off; off = (ni==5)?o6:off; off = (ni==6)?o7:off;
  off = (ni==7)?o8:off;
  float4 v = *(const float4*)(g_imt + off*CC + (lane&3)*4);
#pragma unroll
  for(int o=4;o<=16;o<<=1){
    v.x += __shfl_xor_sync(FULL, v.x, o);
    v.y += __shfl_xor_sync(FULL, v.y, o);
    v.z += __shfl_xor_sync(FULL, v.z, o);
    v.w += __shfl_xor_sync(FULL, v.w, o);
  }
  if(lane < 4){
    v.x*=0.125f; v.y*=0.125f; v.z*=0.125f; v.w*=0.125f;
    ((float4*)(g_neigh + n*CC))[lane] = v;
  }
}

// ------------------------- K4: deform attn + fuse + final BN ----------------
__global__ void __launch_bounds__(NT) k_EG(const int* __restrict__ grid,
    const float* __restrict__ Wfc, const float* __restrict__ gfc, const float* __restrict__ betafc,
    const float* __restrict__ gt,  const float* __restrict__ betat,
    const float* __restrict__ Woff,const float* __restrict__ boff,
    const float* __restrict__ Wattn,const float* __restrict__ battn,
    const float* __restrict__ Wout,const float* __restrict__ bout,
    const float* __restrict__ Wf,  const float* __restrict__ bf,
    const float* __restrict__ gf,  const float* __restrict__ betaf,
    float* __restrict__ out){
  __shared__ float sF[40];
  __shared__ float sWoff[CC*32], sWattn[CC*16], sWout[CC*16], sWf[32*CC];
  __shared__ float sboff[32], sbattn[16], sbout[16], sbf[16];
  __shared__ float sa3[16], sb3[16], su0[16], su1[16], sb2[16], sc[2];
  __shared__ float red[4][32];
  __shared__ float sP[32], a4[16], b4[16];
  int b=blockIdx.x, t=threadIdx.x;
  int lane=t&31, w=t>>5;
  if(b==0 && t==0){            // reset SS barriers for next replay
    *(volatile int*)&g_bc[0]=0;
    *(volatile int*)&g_bc[1]=0;
    *(volatile int*)&g_bc[2]=0;
  }
  for(int i=t;i<CC*32;i+=NT) sWoff[i]=Woff[i];
  for(int i=t;i<CC*16;i+=NT){ sWattn[i]=Wattn[i]; sWout[i]=Wout[i]; }
  for(int i=t;i<32*CC;i+=NT) sWf[i]=Wf[i];
  if(t<32) sboff[t]=boff[t];
  if(t<16){ sbattn[t]=battn[t]; sbout[t]=bout[t]; sbf[t]=bf[t]; }
  // warp-parallel reduction of partials
  for(int i=w;i<35;i+=4){
    const float* pp = g_p2 + i*NB;
    float s = pp[lane]+pp[lane+32]+pp[lane+64]+pp[lane+96];
    s = warpSum(s);
    if(!lane) sF[i]=s;
  }
  if(w==0){
    const float* pp = g_p2 + 35*NB;
    float m = fmaxf(fmaxf(pp[lane],pp[lane+32]),fmaxf(pp[lane+64],pp[lane+96]));
    m = warpMax(m);
    if(!lane) sF[35]=m;
  } else if(w==1){
    const float* pp = g_p2 + 36*NB;
    float m = fmaxf(fmaxf(pp[lane],pp[lane+32]),fmaxf(pp[lane+64],pp[lane+96]));
    m = warpMax(m);
    if(!lane) sF[36]=m;
  } else if(w==2){
    const float* pp = g_pA + 32*NB;
    float s = pp[lane]+pp[lane+32]+pp[lane+64]+pp[lane+96];
    s = warpSum(s);
    if(!lane) sF[37]=s;
  } else {
    const float* pp = g_pA + 33*NB;
    float s = pp[lane]+pp[lane+32]+pp[lane+64]+pp[lane+96];
    s = warpSum(s);
    if(!lane) sF[38]=s;
  }
  __syncthreads();
  if(t<16){
    float m3 = sF[t]*INVN;
    float v3 = sF[16+t]*INVN - m3*m3;
    float is3 = rsqrtf(v3+EPSBN);
    sa3[t] = is3*gt[t];
    sb3[t] = betat[t] - m3*is3*gt[t];
    float mxy = sF[35]; if(mxy==0.f) mxy=1.f;
    float mxx = sF[36]; if(mxx==0.f) mxx=1.f;
    float Syy=sF[32]*INVN, Sxx=sF[33]*INVN, Sxy=sF[34]*INVN;
    float w0 = Wfc[t]/mxy;
    float w1 = Wfc[16+t]/mxx;
    float v2 = w0*w0*Syy + 2.f*w0*w1*Sxy + w1*w1*Sxx;
    float a2 = rsqrtf(v2+EPSBN)*gfc[t];
    su0[t]=w0*a2; su1[t]=w1*a2; sb2[t]=betafc[t];
  }
  if(t==16){ sc[0]=sF[37]*INVN; sc[1]=sF[38]*INVN; }
  __syncthreads();

  int n = b*NT + t;
  int qyi = grid[2*n], qxi = grid[2*n+1];
  float gy=(float)qyi, gx=(float)qxi;
  float ry=gy-sc[0], rx=gx-sc[1];
  float q[16];
#pragma unroll
  for(int c=0;c<16;c++)
    q[c] = g_pts[n*CC+c] + ry*su0[c] + rx*su1[c] + sb2[c];

  float a[16];
#pragma unroll
  for(int hp=0;hp<16;hp++){
    float l=sbattn[hp];
#pragma unroll
    for(int c=0;c<16;c++) l += q[c]*sWattn[c*16+hp];
    a[hp]=l;
  }
#pragma unroll
  for(int h=0;h<4;h++){
    float m=fmaxf(fmaxf(a[4*h],a[4*h+1]),fmaxf(a[4*h+2],a[4*h+3]));
    float e0=expf(a[4*h]-m), e1=expf(a[4*h+1]-m), e2=expf(a[4*h+2]-m), e3=expf(a[4*h+3]-m);
    float inv=1.f/(e0+e1+e2+e3);
    a[4*h]=e0*inv; a[4*h+1]=e1*inv; a[4*h+2]=e2*inv; a[4*h+3]=e3*inv;
  }

  float acc[16];
#pragma unroll
  for(int c=0;c<16;c++) acc[c]=0.f;

#define CORNER(Yf,Xf,Wgt) do{ \
    float _y=(Yf), _x=(Xf); \
    if(_y>=0.f && _y<=(float)(HH-1) && _x>=0.f && _x<=(float)(WW-1)){ \
      int _i = ((int)_y)*WW + (int)_x; \
      const float4 _v = *(const float4*)(g_val + _i*CC + h*4); \
      float _w=(Wgt); \
      acc[h*4+0]+=_w*_v.x; acc[h*4+1]+=_w*_v.y; acc[h*4+2]+=_w*_v.z; acc[h*4+3]+=_w*_v.w; \
    } }while(0)

#pragma unroll
  for(int h=0;h<4;h++){
#pragma unroll
    for(int p=0;p<4;p++){
      float offy=sboff[h*8+p*2], offx=sboff[h*8+p*2+1];
#pragma unroll
      for(int c=0;c<16;c++){
        offy += q[c]*sWoff[c*32 + h*8+p*2];
        offx += q[c]*sWoff[c*32 + h*8+p*2+1];
      }
      float ly=gy+offy, lx=gx+offx;
      float fy=floorf(ly), fx=floorf(lx);
      float wy=ly-fy, wx=lx-fx;
      float ap=a[h*4+p];
      CORNER(fy,     fx,     ap*(1.f-wy)*(1.f-wx));
      CORNER(fy,     fx+1.f, ap*(1.f-wy)*wx);
      CORNER(fy+1.f, fx,     ap*wy*(1.f-wx));
      CORNER(fy+1.f, fx+1.f, ap*wy*wx);
    }
  }
#undef CORNER

  const float* nbp = g_neigh + n*CC;
  float img[16];
#pragma unroll
  for(int c=0;c<16;c++){
    float s=sbout[c];
#pragma unroll
    for(int k=0;k<16;k++) s += acc[k]*sWout[k*16+c];
    img[c] = s + nbp[c];
  }
  float pp2[16];
#pragma unroll
  for(int c=0;c<16;c++) pp2[c] = g_Y3[n*CC+c]*sa3[c] + sb3[c];

  float y4[16];
#pragma unroll
  for(int c=0;c<16;c++){
    float s=sbf[c];
#pragma unroll
    for(int k=0;k<16;k++) s += fmaxf(pp2[k],0.f)*sWf[k*16+c];
#pragma unroll
    for(int k=0;k<16;k++) s += fmaxf(img[k],0.f)*sWf[(16+k)*16+c];
    y4[c]=s;
  }
#pragma unroll
  for(int c=0;c<16;c++){ float s=warpSum(y4[c]);        if(!lane) red[w][c]=s; }
#pragma unroll
  for(int c=0;c<16;c++){ float s=warpSum(y4[c]*y4[c]);  if(!lane) red[w][16+c]=s; }
  __syncthreads();
  if(t<32) g_p3[t*NB+b] = red[0][t]+red[1][t]+red[2][t]+red[3][t];

  gbar(3);

  // ---- G phase: final BN + relu, y4 still in registers ----
  for(int i=w;i<32;i+=4){
    const float* pp = g_p3 + i*NB;
    float s = pp[lane]+pp[lane+32]+pp[lane+64]+pp[lane+96];
    s = warpSum(s);
    if(!lane) sP[i]=s;
  }
  __syncthreads();
  if(t<16){
    float m = sP[t]*INVN;
    float vv = sP[16+t]*INVN - m*m;
    float is = rsqrtf(vv+EPSBN);
    a4[t]=is*gf[t];
    b4[t]=betaf[t] - m*is*gf[t];
  }
  __syncthreads();
#pragma unroll
  for(int c=0;c<16;c++)
    out[n*CC+c] = fmaxf(y4[c]*a4[c] + b4[c], 0.f);
}

// ------------------------- launch ------------------------------------------
extern "C" void kernel_launch(void* const* d_in, const int* in_sizes, int n_in,
                              void* d_out, int out_size){
  const float* pf     = (const float*)d_in[0];
  const float* imf    = (const float*)d_in[1];
  const int*   grid   = (const int*)  d_in[2];
  const float* Wk     = (const float*)d_in[3];
  const float* bk     = (const float*)d_in[4];
  const float* gk     = (const float*)d_in[5];
  const float* betak  = (const float*)d_in[6];
  const float* Wfc    = (const float*)d_in[7];
  /* bfc = d_in[8] cancels analytically */
  const float* gfc    = (const float*)d_in[9];
  const float* betafc = (const float*)d_in[10];
  const float* Wt     = (const float*)d_in[11];
  const float* bt     = (const float*)d_in[12];
  const float* gt     = (const float*)d_in[13];
  const float* betat  = (const float*)d_in[14];
  const float* Woff   = (const float*)d_in[15];
  const float* boff   = (const float*)d_in[16];
  const float* Wattn  = (const float*)d_in[17];
  const float* battn  = (const float*)d_in[18];
  const float* Wval   = (const float*)d_in[19];
  const float* bval   = (const float*)d_in[20];
  const float* Wout   = (const float*)d_in[21];
  const float* bout   = (const float*)d_in[22];
  const float* Wf     = (const float*)d_in[23];
  const float* bf     = (const float*)d_in[24];
  const float* gf     = (const float*)d_in[25];
  const float* betaf  = (const float*)d_in[26];
  float* out = (float*)d_out;

  k_init<<<HWIMG/NT, NT>>>(imf, Wval, bval);
  k_SS  <<<NB, NT>>>(pf, grid, Wk, bk, gk, betak, Wt, bt);
  k_knn <<<NPTS/4, 128>>>(grid);
  k_EG  <<<NB, NT>>>(grid, Wfc, gfc, betafc, gt, betat,
                     Woff, boff, Wattn, battn, Wout, bout, Wf, bf,
                     gf, betaf, out);
}